// round 1
// baseline (speedup 1.0000x reference)
#include <cuda_runtime.h>

// ---------------------------------------------------------------------------
// BilinearAttention:
//   interm = Q @ W                         (B*N, H) x (H, H)
//   e      = relu(interm @ V^T)            per batch: (N,H) x (N,H)^T
//   logits = mask>0 ? e : -1e9
//   attn   = softmax(logits, axis=-1)      rows of length N
//   out    = attn @ V                      per batch: (N,N) x (N,H)
// Output buffer: [ out (B*N*H) | attn (B*N*N) ]  (tuple order)
// ---------------------------------------------------------------------------

#define B_   8
#define N_   2048
#define H_   1024

#define BM 128
#define BN 128
#define BK 8
#define TM 8
#define TN 8

// 64 MB scratch for interm = Q @ W  (allocation-free requirement)
__device__ float g_interm[(size_t)B_ * N_ * H_];

template<bool TRANS_B, bool RELU_MASK>
__global__ __launch_bounds__(256, 2)
void gemm_kernel(const float* __restrict__ A, const float* __restrict__ B,
                 float* __restrict__ C, const int* __restrict__ Mask,
                 int M, int N, int K,
                 size_t strideA, size_t strideB, size_t strideC, size_t strideMask)
{
    __shared__ float As[BK][BM];   // A tile, stored transposed (k-major)
    __shared__ float Bs[BK][BN];   // B tile, k-major

    const int tid = threadIdx.x;
    const int tx  = tid & 15;      // 0..15  -> N direction
    const int ty  = tid >> 4;      // 0..15  -> M direction
    const int bm  = blockIdx.y * BM;
    const int bn  = blockIdx.x * BN;
    const int bz  = blockIdx.z;

    A += (size_t)bz * strideA;
    B += (size_t)bz * strideB;
    C += (size_t)bz * strideC;

    // A tile load mapping: 128 rows x 8 k = 1024 floats = 256 float4
    const int arow = tid >> 1;           // 0..127
    const int acol = (tid & 1) * 4;      // 0 or 4
    // B tile (NN): 8 k-rows x 128 n
    const int brow_nn = tid >> 5;        // 0..7
    const int bcol_nn = (tid & 31) * 4;  // 0..124
    // B tile (NT): 128 n-rows x 8 k
    const int brow_nt = tid >> 1;        // n 0..127
    const int bcol_nt = (tid & 1) * 4;   // k 0 or 4

    float acc[TM][TN];
#pragma unroll
    for (int i = 0; i < TM; i++)
#pragma unroll
        for (int j = 0; j < TN; j++) acc[i][j] = 0.f;

    const float* Aload = A + (size_t)(bm + arow) * K + acol;
    const float* Bload;
    if (TRANS_B) Bload = B + (size_t)(bn + brow_nt) * K + bcol_nt;
    else         Bload = B + (size_t)brow_nn * N + bn + bcol_nn;

    for (int k0 = 0; k0 < K; k0 += BK) {
        float4 av = *reinterpret_cast<const float4*>(Aload + k0);
        As[acol + 0][arow] = av.x;
        As[acol + 1][arow] = av.y;
        As[acol + 2][arow] = av.z;
        As[acol + 3][arow] = av.w;

        if (TRANS_B) {
            float4 bv = *reinterpret_cast<const float4*>(Bload + k0);
            Bs[bcol_nt + 0][brow_nt] = bv.x;
            Bs[bcol_nt + 1][brow_nt] = bv.y;
            Bs[bcol_nt + 2][brow_nt] = bv.z;
            Bs[bcol_nt + 3][brow_nt] = bv.w;
        } else {
            float4 bv = *reinterpret_cast<const float4*>(Bload + (size_t)k0 * N);
            *reinterpret_cast<float4*>(&Bs[brow_nn][bcol_nn]) = bv;
        }
        __syncthreads();

#pragma unroll
        for (int k = 0; k < BK; k++) {
            float a_frag[TM], b_frag[TN];
            *reinterpret_cast<float4*>(&a_frag[0]) =
                *reinterpret_cast<const float4*>(&As[k][ty * TM]);
            *reinterpret_cast<float4*>(&a_frag[4]) =
                *reinterpret_cast<const float4*>(&As[k][ty * TM + 4]);
            *reinterpret_cast<float4*>(&b_frag[0]) =
                *reinterpret_cast<const float4*>(&Bs[k][tx * TN]);
            *reinterpret_cast<float4*>(&b_frag[4]) =
                *reinterpret_cast<const float4*>(&Bs[k][tx * TN + 4]);
#pragma unroll
            for (int i = 0; i < TM; i++)
#pragma unroll
                for (int j = 0; j < TN; j++)
                    acc[i][j] += a_frag[i] * b_frag[j];
        }
        __syncthreads();
    }

    // Epilogue
#pragma unroll
    for (int i = 0; i < TM; i++) {
        const int row = bm + ty * TM + i;
#pragma unroll
        for (int j = 0; j < TN; j += 4) {
            const int col = bn + tx * TN + j;
            float4 v = make_float4(acc[i][j], acc[i][j + 1], acc[i][j + 2], acc[i][j + 3]);
            if (RELU_MASK) {
                const int4 mk = *reinterpret_cast<const int4*>(
                    Mask + (size_t)bz * strideMask + (size_t)row * N + col);
                v.x = mk.x > 0 ? fmaxf(v.x, 0.f) : -1e9f;
                v.y = mk.y > 0 ? fmaxf(v.y, 0.f) : -1e9f;
                v.z = mk.z > 0 ? fmaxf(v.z, 0.f) : -1e9f;
                v.w = mk.w > 0 ? fmaxf(v.w, 0.f) : -1e9f;
            }
            *reinterpret_cast<float4*>(&C[(size_t)row * N + col]) = v;
        }
    }
}

// In-place row softmax over rows of length N (N = 2048 here).
__global__ __launch_bounds__(256)
void softmax_kernel(float* __restrict__ attn, int N)
{
    const size_t row = blockIdx.x;
    float* p = attn + row * (size_t)N;
    const int tid = threadIdx.x;
    __shared__ float red[256];

    float lmax = -3.4e38f;
    for (int i = tid; i < N; i += 256) lmax = fmaxf(lmax, p[i]);
    red[tid] = lmax;
    __syncthreads();
#pragma unroll
    for (int s = 128; s > 0; s >>= 1) {
        if (tid < s) red[tid] = fmaxf(red[tid], red[tid + s]);
        __syncthreads();
    }
    const float rmax = red[0];
    __syncthreads();

    float lsum = 0.f;
    for (int i = tid; i < N; i += 256) {
        float v = __expf(p[i] - rmax);
        p[i] = v;
        lsum += v;
    }
    red[tid] = lsum;
    __syncthreads();
#pragma unroll
    for (int s = 128; s > 0; s >>= 1) {
        if (tid < s) red[tid] += red[tid + s];
        __syncthreads();
    }
    const float inv = 1.0f / red[0];
    __syncthreads();

    for (int i = tid; i < N; i += 256) p[i] *= inv;
}

extern "C" void kernel_launch(void* const* d_in, const int* in_sizes, int n_in,
                              void* d_out, int out_size)
{
    const float* query = (const float*)d_in[0];   // (B, N, H)
    const float* value = (const float*)d_in[1];   // (B, N, H)
    const int*   mask  = (const int*)d_in[2];     // (B, N, N)
    const float* W     = (const float*)d_in[3];   // (H, H)

    float* out  = (float*)d_out;                       // (B, N, H)
    float* attn = out + (size_t)B_ * N_ * H_;          // (B, N, N)

    float* interm = nullptr;
    cudaGetSymbolAddress((void**)&interm, g_interm);

    const dim3 blk(256);

    // GEMM1: interm = Q @ W   (one big GEMM: M = B*N, N = H, K = H)
    {
        dim3 grid(H_ / BN, (B_ * N_) / BM, 1);
        gemm_kernel<false, false><<<grid, blk>>>(
            query, W, interm, nullptr,
            B_ * N_, H_, H_, 0, 0, 0, 0);
    }

    // GEMM2: logits = mask>0 ? relu(interm @ V^T) : -1e9   (batched NT)
    {
        dim3 grid(N_ / BN, N_ / BM, B_);
        gemm_kernel<true, true><<<grid, blk>>>(
            interm, value, attn, mask,
            N_, N_, H_,
            (size_t)N_ * H_, (size_t)N_ * H_, (size_t)N_ * N_, (size_t)N_ * N_);
    }

    // Softmax in place over attn rows
    softmax_kernel<<<B_ * N_, 256>>>(attn, N_);

    // GEMM3: out = attn @ V   (batched NN, K = N)
    {
        dim3 grid(H_ / BN, N_ / BM, B_);
        gemm_kernel<false, false><<<grid, blk>>>(
            attn, value, out, nullptr,
            N_, H_, N_,
            (size_t)N_ * N_, (size_t)N_ * H_, (size_t)N_ * H_, 0);
    }
}

// round 3
// speedup vs baseline: 2.1896x; 2.1896x over previous
#include <cuda_runtime.h>
#include <cuda_bf16.h>
#include <cstdint>

// ---------------------------------------------------------------------------
// BilinearAttention via mma.sync (HMMA) split-bf16, sm_103-safe PTX only.
//   interm = Q @ W                  GEMM1 (epilogue: split to bf16 hi/lo)
//   logits = mask/relu(interm@V^T)  GEMM2 (epilogue: mask+relu, fp32)
//   attn   = softmax(logits)        (fused split-bf16 emit)
//   out    = attn @ V               GEMM3 (fp32)
// Each GEMM: C = Ah*Bh + Al*Bh + Ah*Bl  (three K-segments, one accumulator).
// Output buffer: [ out (B*N*H) | attn (B*N*N) ]
// ---------------------------------------------------------------------------

#define B_   8
#define N_   2048
#define H_   1024

// ------------------------- scratch (no allocations) -------------------------
__device__ __nv_bfloat16 g_Qh[(size_t)B_ * N_ * H_];
__device__ __nv_bfloat16 g_Ql[(size_t)B_ * N_ * H_];
__device__ __nv_bfloat16 g_Wth[(size_t)H_ * H_];
__device__ __nv_bfloat16 g_Wtl[(size_t)H_ * H_];
__device__ __nv_bfloat16 g_Vh[(size_t)B_ * N_ * H_];
__device__ __nv_bfloat16 g_Vl[(size_t)B_ * N_ * H_];
__device__ __nv_bfloat16 g_VTh[(size_t)B_ * H_ * N_];
__device__ __nv_bfloat16 g_VTl[(size_t)B_ * H_ * N_];
__device__ __nv_bfloat16 g_Ih[(size_t)B_ * N_ * H_];
__device__ __nv_bfloat16 g_Il[(size_t)B_ * N_ * H_];
__device__ __nv_bfloat16 g_ATh[(size_t)B_ * N_ * N_];
__device__ __nv_bfloat16 g_ATl[(size_t)B_ * N_ * N_];

// ----------------------------- PTX primitives -------------------------------
__device__ __forceinline__ uint32_t smem_u32(const void* p) {
    uint32_t a;
    asm("{ .reg .u64 t; cvta.to.shared.u64 t, %1; cvt.u32.u64 %0, t; }"
        : "=r"(a) : "l"(p));
    return a;
}

__device__ __forceinline__ void cp16(uint32_t dst, const void* src) {
    asm volatile("cp.async.cg.shared.global [%0], [%1], 16;" :: "r"(dst), "l"(src));
}
__device__ __forceinline__ void cp_commit() {
    asm volatile("cp.async.commit_group;" ::: "memory");
}
template<int Nn>
__device__ __forceinline__ void cp_wait() {
    asm volatile("cp.async.wait_group %0;" :: "n"(Nn) : "memory");
}

__device__ __forceinline__ void ldm_x4(uint32_t& r0, uint32_t& r1, uint32_t& r2,
                                       uint32_t& r3, uint32_t addr) {
    asm volatile("ldmatrix.sync.aligned.m8n8.x4.shared.b16 {%0,%1,%2,%3}, [%4];"
                 : "=r"(r0), "=r"(r1), "=r"(r2), "=r"(r3) : "r"(addr));
}

__device__ __forceinline__ void mma16816(float* c, const uint32_t* a, const uint32_t* b) {
    asm volatile(
        "mma.sync.aligned.m16n8k16.row.col.f32.bf16.bf16.f32 "
        "{%0,%1,%2,%3}, {%4,%5,%6,%7}, {%8,%9}, {%0,%1,%2,%3};"
        : "+f"(c[0]), "+f"(c[1]), "+f"(c[2]), "+f"(c[3])
        : "r"(a[0]), "r"(a[1]), "r"(a[2]), "r"(a[3]), "r"(b[0]), "r"(b[1]));
}

// ---------------------- split-bf16 tensor-core GEMM --------------------------
// C[M,Ncols] = Ah*Bh + Al*Bh + Ah*Bl.  A:[M,K] row-major, B:[Ncols,K] row-major.
// CTA tile 128x128, BK=64, double-buffered cp.async, 8 warps of 32x64.
// EPI: 0 = split bf16 hi/lo; 1 = mask+relu fp32; 2 = plain fp32.
#define TILE_BYTES 16384           // 128 rows x 128B (64 bf16)
#define BUF_BYTES  (2 * TILE_BYTES)
#define SMEM_BYTES (2 * BUF_BYTES) // 64 KB

template<int EPI>
__global__ __launch_bounds__(256, 2)
void gemm_sp(const __nv_bfloat16* __restrict__ Ah, const __nv_bfloat16* __restrict__ Al,
             const __nv_bfloat16* __restrict__ Bh, const __nv_bfloat16* __restrict__ Bl,
             float* __restrict__ Cf,
             __nv_bfloat16* __restrict__ Ch, __nv_bfloat16* __restrict__ Cl,
             const int* __restrict__ Mask,
             int K, int ldc,
             size_t sA, size_t sB, size_t sC, size_t sM)
{
    extern __shared__ __align__(1024) char smem[];
    const uint32_t sbase = smem_u32(smem);
    const int tid  = threadIdx.x;
    const int wid  = tid >> 5;
    const int lane = tid & 31;
    const int bm = blockIdx.y * 128;
    const int bn = blockIdx.x * 128;
    const int bz = blockIdx.z;

    Ah += (size_t)bz * sA;  Al += (size_t)bz * sA;
    Bh += (size_t)bz * sB;  Bl += (size_t)bz * sB;

    const __nv_bfloat16* asg[3] = {Ah, Al, Ah};
    const __nv_bfloat16* bsg[3] = {Bh, Bh, Bl};
    const int cps = K >> 6;         // 64-wide chunks per segment
    const int nc  = 3 * cps;

    const int warpM = wid >> 1;     // 0..3  -> M offset *32
    const int warpN = wid & 1;      // 0..1  -> N offset *64

    // cp.async mapping: row = tid>>1 (0..127), 4 consecutive 16B segs per thread
    const int ldrow  = tid >> 1;
    const int ldseg0 = (tid & 1) * 4;
    const uint32_t swrow = (uint32_t)(ldrow & 7);

    float acc[2][8][4];
#pragma unroll
    for (int i = 0; i < 2; i++)
#pragma unroll
        for (int j = 0; j < 8; j++)
#pragma unroll
            for (int q = 0; q < 4; q++) acc[i][j][q] = 0.f;

    auto load_chunk = [&](int c) {
        const int seg = c / cps;
        const int kk  = (c - seg * cps) * 64;
        const __nv_bfloat16* ap = asg[seg];
        const __nv_bfloat16* bp = bsg[seg];
        const uint32_t sa = sbase + (uint32_t)(c & 1) * BUF_BYTES;
        const uint32_t sb = sa + TILE_BYTES;
        const __nv_bfloat16* arow = ap + (size_t)(bm + ldrow) * K + kk;
        const __nv_bfloat16* brow = bp + (size_t)(bn + ldrow) * K + kk;
#pragma unroll
        for (int s = 0; s < 4; ++s) {
            const uint32_t segi = ldseg0 + s;
            const uint32_t off  = (uint32_t)ldrow * 128 + ((segi ^ swrow) << 4);
            cp16(sa + off, arow + segi * 8);
            cp16(sb + off, brow + segi * 8);
        }
        cp_commit();
    };

    // ldmatrix per-lane address components (constant across chunks)
    const uint32_t aRow = (uint32_t)(warpM * 32 + (lane & 15));   // + mt*16
    const uint32_t aKhi = (uint32_t)(lane >> 4);                  // k-seg select
    const uint32_t bRow = (uint32_t)(warpN * 64 + ((lane & 16) >> 1) + (lane & 7)); // + nb*16
    const uint32_t bKhi = (uint32_t)((lane >> 3) & 1);

    auto compute_chunk = [&](int buf) {
        const uint32_t sa = sbase + (uint32_t)buf * BUF_BYTES;
        const uint32_t sb = sa + TILE_BYTES;
#pragma unroll
        for (int ks = 0; ks < 4; ++ks) {
            uint32_t a[2][4];
#pragma unroll
            for (int mt = 0; mt < 2; ++mt) {
                const uint32_t row = aRow + mt * 16;
                const uint32_t seg = ((uint32_t)(ks * 2) + aKhi) ^ (row & 7);
                ldm_x4(a[mt][0], a[mt][1], a[mt][2], a[mt][3],
                       sa + row * 128 + (seg << 4));
            }
            uint32_t b[8][2];
#pragma unroll
            for (int nb = 0; nb < 4; ++nb) {
                const uint32_t row = bRow + nb * 16;
                const uint32_t seg = ((uint32_t)(ks * 2) + bKhi) ^ (row & 7);
                ldm_x4(b[nb * 2][0], b[nb * 2][1], b[nb * 2 + 1][0], b[nb * 2 + 1][1],
                       sb + row * 128 + (seg << 4));
            }
#pragma unroll
            for (int mt = 0; mt < 2; ++mt)
#pragma unroll
                for (int nt = 0; nt < 8; ++nt)
                    mma16816(acc[mt][nt], a[mt], b[nt]);
        }
    };

    load_chunk(0);
    load_chunk(1);
    for (int c = 0; c < nc; ++c) {
        if (c + 2 < nc) cp_wait<1>(); else cp_wait<0>();
        __syncthreads();
        compute_chunk(c & 1);
        __syncthreads();
        if (c + 2 < nc) load_chunk(c + 2);
    }

    // ------------------------------ epilogue --------------------------------
    const int rBase = bm + warpM * 32 + (lane >> 2);
    const int cBase = bn + warpN * 64 + (lane & 3) * 2;
#pragma unroll
    for (int mt = 0; mt < 2; ++mt) {
#pragma unroll
        for (int half = 0; half < 2; ++half) {
            const int row = rBase + mt * 16 + half * 8;
#pragma unroll
            for (int nt = 0; nt < 8; ++nt) {
                const int col = cBase + nt * 8;
                const float v0 = acc[mt][nt][half * 2 + 0];
                const float v1 = acc[mt][nt][half * 2 + 1];
                if (EPI == 0) {
                    __nv_bfloat16 hv[2], lv[2];
                    hv[0] = __float2bfloat16(v0);
                    lv[0] = __float2bfloat16(v0 - __bfloat162float(hv[0]));
                    hv[1] = __float2bfloat16(v1);
                    lv[1] = __float2bfloat16(v1 - __bfloat162float(hv[1]));
                    *reinterpret_cast<uint32_t*>(Ch + (size_t)row * ldc + col) =
                        *reinterpret_cast<const uint32_t*>(hv);
                    *reinterpret_cast<uint32_t*>(Cl + (size_t)row * ldc + col) =
                        *reinterpret_cast<const uint32_t*>(lv);
                } else if (EPI == 1) {
                    const int2 m = *reinterpret_cast<const int2*>(
                        Mask + (size_t)bz * sM + (size_t)row * ldc + col);
                    float2 v;
                    v.x = m.x > 0 ? fmaxf(v0, 0.f) : -1e9f;
                    v.y = m.y > 0 ? fmaxf(v1, 0.f) : -1e9f;
                    *reinterpret_cast<float2*>(
                        Cf + (size_t)bz * sC + (size_t)row * ldc + col) = v;
                } else {
                    float2 v; v.x = v0; v.y = v1;
                    *reinterpret_cast<float2*>(
                        Cf + (size_t)bz * sC + (size_t)row * ldc + col) = v;
                }
            }
        }
    }
}

// --------------------------- conversion kernels -----------------------------
__global__ __launch_bounds__(256)
void split_kernel(const float* __restrict__ x, __nv_bfloat16* __restrict__ h,
                  __nv_bfloat16* __restrict__ l, size_t n)
{
    const size_t i = ((size_t)blockIdx.x * blockDim.x + threadIdx.x) * 4;
    if (i >= n) return;
    const float4 v = *reinterpret_cast<const float4*>(x + i);
    __nv_bfloat16 hv[4], lv[4];
    const float vv[4] = {v.x, v.y, v.z, v.w};
#pragma unroll
    for (int j = 0; j < 4; ++j) {
        const __nv_bfloat16 hh = __float2bfloat16(vv[j]);
        hv[j] = hh;
        lv[j] = __float2bfloat16(vv[j] - __bfloat162float(hh));
    }
    *reinterpret_cast<uint2*>(h + i) = *reinterpret_cast<const uint2*>(hv);
    *reinterpret_cast<uint2*>(l + i) = *reinterpret_cast<const uint2*>(lv);
}

// out[b, c, r] = split(in[b, r, c]);  in: [B, R, C]
__global__ __launch_bounds__(1024)
void tsplit_kernel(const float* __restrict__ x, __nv_bfloat16* __restrict__ ht,
                   __nv_bfloat16* __restrict__ lt, int R, int C)
{
    __shared__ float t[32][33];
    const size_t boff = (size_t)blockIdx.z * R * C;
    const int r0 = blockIdx.y * 32, c0 = blockIdx.x * 32;
    t[threadIdx.y][threadIdx.x] =
        x[boff + (size_t)(r0 + threadIdx.y) * C + c0 + threadIdx.x];
    __syncthreads();
    const float v = t[threadIdx.x][threadIdx.y];
    const __nv_bfloat16 h = __float2bfloat16(v);
    const size_t o = boff + (size_t)(c0 + threadIdx.y) * R + r0 + threadIdx.x;
    ht[o] = h;
    lt[o] = __float2bfloat16(v - __bfloat162float(h));
}

// softmax in place over rows of length N; also emits split bf16 attn
__global__ __launch_bounds__(256)
void softmax_split_kernel(float* __restrict__ attn, __nv_bfloat16* __restrict__ ah,
                          __nv_bfloat16* __restrict__ al, int N)
{
    const size_t row = blockIdx.x;
    float* p = attn + row * (size_t)N;
    __nv_bfloat16* ph = ah + row * (size_t)N;
    __nv_bfloat16* pl = al + row * (size_t)N;
    const int tid = threadIdx.x;
    __shared__ float red[256];

    float lmax = -3.4e38f;
    for (int i = tid; i < N; i += 256) lmax = fmaxf(lmax, p[i]);
    red[tid] = lmax;
    __syncthreads();
#pragma unroll
    for (int s = 128; s > 0; s >>= 1) {
        if (tid < s) red[tid] = fmaxf(red[tid], red[tid + s]);
        __syncthreads();
    }
    const float rmax = red[0];
    __syncthreads();

    float lsum = 0.f;
    for (int i = tid; i < N; i += 256) {
        const float v = __expf(p[i] - rmax);
        p[i] = v;
        lsum += v;
    }
    red[tid] = lsum;
    __syncthreads();
#pragma unroll
    for (int s = 128; s > 0; s >>= 1) {
        if (tid < s) red[tid] += red[tid + s];
        __syncthreads();
    }
    const float inv = 1.0f / red[0];
    __syncthreads();

    for (int i = tid; i < N; i += 256) {
        const float v = p[i] * inv;
        p[i] = v;
        const __nv_bfloat16 h = __float2bfloat16(v);
        ph[i] = h;
        pl[i] = __float2bfloat16(v - __bfloat162float(h));
    }
}

// --------------------------------- launch -----------------------------------
extern "C" void kernel_launch(void* const* d_in, const int* in_sizes, int n_in,
                              void* d_out, int out_size)
{
    const float* query = (const float*)d_in[0];   // (B, N, H)
    const float* value = (const float*)d_in[1];   // (B, N, H)
    const int*   mask  = (const int*)d_in[2];     // (B, N, N)
    const float* W     = (const float*)d_in[3];   // (H, H)

    float* out  = (float*)d_out;                   // (B, N, H)
    float* attn = out + (size_t)B_ * N_ * H_;      // (B, N, N)

    __nv_bfloat16 *Qh, *Ql, *Wth, *Wtl, *Vh, *Vl, *VTh, *VTl, *Ih, *Il, *ATh, *ATl;
    cudaGetSymbolAddress((void**)&Qh,  g_Qh);
    cudaGetSymbolAddress((void**)&Ql,  g_Ql);
    cudaGetSymbolAddress((void**)&Wth, g_Wth);
    cudaGetSymbolAddress((void**)&Wtl, g_Wtl);
    cudaGetSymbolAddress((void**)&Vh,  g_Vh);
    cudaGetSymbolAddress((void**)&Vl,  g_Vl);
    cudaGetSymbolAddress((void**)&VTh, g_VTh);
    cudaGetSymbolAddress((void**)&VTl, g_VTl);
    cudaGetSymbolAddress((void**)&Ih,  g_Ih);
    cudaGetSymbolAddress((void**)&Il,  g_Il);
    cudaGetSymbolAddress((void**)&ATh, g_ATh);
    cudaGetSymbolAddress((void**)&ATl, g_ATl);

    cudaFuncSetAttribute(gemm_sp<0>, cudaFuncAttributeMaxDynamicSharedMemorySize, SMEM_BYTES);
    cudaFuncSetAttribute(gemm_sp<1>, cudaFuncAttributeMaxDynamicSharedMemorySize, SMEM_BYTES);
    cudaFuncSetAttribute(gemm_sp<2>, cudaFuncAttributeMaxDynamicSharedMemorySize, SMEM_BYTES);

    const size_t nQ = (size_t)B_ * N_ * H_;

    // Split Q, V; transpose+split W, V
    split_kernel<<<(unsigned)(nQ / 4 / 256), 256>>>(query, Qh, Ql, nQ);
    split_kernel<<<(unsigned)(nQ / 4 / 256), 256>>>(value, Vh, Vl, nQ);
    tsplit_kernel<<<dim3(H_ / 32, H_ / 32, 1), dim3(32, 32)>>>(W, Wth, Wtl, H_, H_);
    tsplit_kernel<<<dim3(H_ / 32, N_ / 32, B_), dim3(32, 32)>>>(value, VTh, VTl, N_, H_);

    // GEMM1: interm = Q @ W -> split bf16   (M=B*N, Ncols=H, K=H)
    gemm_sp<0><<<dim3(H_ / 128, (B_ * N_) / 128, 1), 256, SMEM_BYTES>>>(
        Qh, Ql, Wth, Wtl, nullptr, Ih, Il, nullptr,
        H_, H_, 0, 0, 0, 0);

    // GEMM2: logits = mask>0 ? relu(interm @ V^T) : -1e9  (fp32 into attn)
    gemm_sp<1><<<dim3(N_ / 128, N_ / 128, B_), 256, SMEM_BYTES>>>(
        Ih, Il, Vh, Vl, attn, nullptr, nullptr, mask,
        H_, N_,
        (size_t)N_ * H_, (size_t)N_ * H_, (size_t)N_ * N_, (size_t)N_ * N_);

    // softmax in place + split bf16 attn
    softmax_split_kernel<<<B_ * N_, 256>>>(attn, ATh, ATl, N_);

    // GEMM3: out = attn @ V   (B given as V^T rows: vt[b,h,n], K = N)
    gemm_sp<2><<<dim3(H_ / 128, N_ / 128, B_), 256, SMEM_BYTES>>>(
        ATh, ATl, VTh, VTl, out, nullptr, nullptr, nullptr,
        N_, H_,
        (size_t)N_ * N_, (size_t)H_ * N_, (size_t)N_ * H_, 0);
}

// round 4
// speedup vs baseline: 3.0070x; 1.3733x over previous
#include <cuda_runtime.h>
#include <cuda_bf16.h>
#include <cstdint>

// ---------------------------------------------------------------------------
// BilinearAttention via mma.sync (HMMA) split-bf16, sm_103-safe PTX only.
// Split GEMM: C = Ah*Bh + Al*Bh + Ah*Bl, with all 4 tiles loaded ONCE per
// K-chunk and 3 MMA passes run from shared memory (traffic-optimal).
// CTA tile 128x256, BK=64, 512 threads, double-buffered cp.async (192KB).
// ---------------------------------------------------------------------------

#define B_   8
#define N_   2048
#define H_   1024

// ------------------------- scratch (no allocations) -------------------------
__device__ __nv_bfloat16 g_Qh[(size_t)B_ * N_ * H_];
__device__ __nv_bfloat16 g_Ql[(size_t)B_ * N_ * H_];
__device__ __nv_bfloat16 g_Wth[(size_t)H_ * H_];
__device__ __nv_bfloat16 g_Wtl[(size_t)H_ * H_];
__device__ __nv_bfloat16 g_Vh[(size_t)B_ * N_ * H_];
__device__ __nv_bfloat16 g_Vl[(size_t)B_ * N_ * H_];
__device__ __nv_bfloat16 g_VTh[(size_t)B_ * H_ * N_];
__device__ __nv_bfloat16 g_VTl[(size_t)B_ * H_ * N_];
__device__ __nv_bfloat16 g_Ih[(size_t)B_ * N_ * H_];
__device__ __nv_bfloat16 g_Il[(size_t)B_ * N_ * H_];
__device__ __nv_bfloat16 g_ATh[(size_t)B_ * N_ * N_];
__device__ __nv_bfloat16 g_ATl[(size_t)B_ * N_ * N_];

// ----------------------------- PTX primitives -------------------------------
__device__ __forceinline__ uint32_t smem_u32(const void* p) {
    uint32_t a;
    asm("{ .reg .u64 t; cvta.to.shared.u64 t, %1; cvt.u32.u64 %0, t; }"
        : "=r"(a) : "l"(p));
    return a;
}
__device__ __forceinline__ void cp16(uint32_t dst, const void* src) {
    asm volatile("cp.async.cg.shared.global [%0], [%1], 16;" :: "r"(dst), "l"(src));
}
__device__ __forceinline__ void cp_commit() {
    asm volatile("cp.async.commit_group;" ::: "memory");
}
template<int Nn>
__device__ __forceinline__ void cp_wait() {
    asm volatile("cp.async.wait_group %0;" :: "n"(Nn) : "memory");
}
__device__ __forceinline__ void ldm_x4(uint32_t& r0, uint32_t& r1, uint32_t& r2,
                                       uint32_t& r3, uint32_t addr) {
    asm volatile("ldmatrix.sync.aligned.m8n8.x4.shared.b16 {%0,%1,%2,%3}, [%4];"
                 : "=r"(r0), "=r"(r1), "=r"(r2), "=r"(r3) : "r"(addr));
}
__device__ __forceinline__ void mma16816(float* c, const uint32_t* a, const uint32_t* b) {
    asm volatile(
        "mma.sync.aligned.m16n8k16.row.col.f32.bf16.bf16.f32 "
        "{%0,%1,%2,%3}, {%4,%5,%6,%7}, {%8,%9}, {%0,%1,%2,%3};"
        : "+f"(c[0]), "+f"(c[1]), "+f"(c[2]), "+f"(c[3])
        : "r"(a[0]), "r"(a[1]), "r"(a[2]), "r"(a[3]), "r"(b[0]), "r"(b[1]));
}

// ---------------------- split-bf16 tensor-core GEMM --------------------------
// CTA tile 128(M) x 256(N), BK=64.  16 warps, warp tile 32x64.
// smem stage: Ah(16K) Al(16K) Bh(32K) Bl(32K) = 96KB, double buffered = 192KB.
#define A_T   16384
#define B_T   32768
#define STAGE (2 * A_T + 2 * B_T)
#define SMEM_BYTES (2 * STAGE)

template<int EPI>  // 0: split bf16 hi/lo; 1: mask+relu fp32; 2: plain fp32
__global__ __launch_bounds__(512, 1)
void gemm_sp(const __nv_bfloat16* __restrict__ Ah, const __nv_bfloat16* __restrict__ Al,
             const __nv_bfloat16* __restrict__ Bh, const __nv_bfloat16* __restrict__ Bl,
             float* __restrict__ Cf,
             __nv_bfloat16* __restrict__ Ch, __nv_bfloat16* __restrict__ Cl,
             const int* __restrict__ Mask,
             int K, int ldc,
             size_t sA, size_t sB, size_t sC, size_t sM)
{
    extern __shared__ __align__(1024) char smem[];
    const uint32_t sbase = smem_u32(smem);
    const int tid  = threadIdx.x;
    const int wid  = tid >> 5;
    const int lane = tid & 31;
    const int bm = blockIdx.y * 128;
    const int bn = blockIdx.x * 256;
    const int bz = blockIdx.z;

    Ah += (size_t)bz * sA;  Al += (size_t)bz * sA;
    Bh += (size_t)bz * sB;  Bl += (size_t)bz * sB;

    const int warpM = wid >> 2;    // 0..3 -> *32
    const int warpN = wid & 3;     // 0..3 -> *64
    const int nc = K >> 6;

    float acc[2][8][4];
#pragma unroll
    for (int i = 0; i < 2; i++)
#pragma unroll
        for (int j = 0; j < 8; j++)
#pragma unroll
            for (int q = 0; q < 4; q++) acc[i][j][q] = 0.f;

    auto load_chunk = [&](int c) {
        const int kk = c << 6;
        const uint32_t st = sbase + (uint32_t)(c & 1) * STAGE;
        // A tiles: 128 rows x 8 segs = 1024 segs; 2 per thread
#pragma unroll
        for (int i = 0; i < 2; ++i) {
            const int s = tid + i * 512;
            const int row = s >> 3, col = s & 7;
            const uint32_t off = (uint32_t)row * 128 + ((uint32_t)(col ^ (row & 7)) << 4);
            const size_t g = (size_t)(bm + row) * K + kk + col * 8;
            cp16(st + off, Ah + g);
            cp16(st + A_T + off, Al + g);
        }
        // B tiles: 256 rows x 8 segs = 2048 segs; 4 per thread
#pragma unroll
        for (int i = 0; i < 4; ++i) {
            const int s = tid + i * 512;
            const int row = s >> 3, col = s & 7;
            const uint32_t off = (uint32_t)row * 128 + ((uint32_t)(col ^ (row & 7)) << 4);
            const size_t g = (size_t)(bn + row) * K + kk + col * 8;
            cp16(st + 2 * A_T + off, Bh + g);
            cp16(st + 2 * A_T + B_T + off, Bl + g);
        }
        cp_commit();
    };

    const uint32_t aRow = (uint32_t)(warpM * 32 + (lane & 15));
    const uint32_t aKhi = (uint32_t)(lane >> 4);
    const uint32_t bRow = (uint32_t)(warpN * 64 + ((lane & 16) >> 1) + (lane & 7));
    const uint32_t bKhi = (uint32_t)((lane >> 3) & 1);

    auto compute_chunk = [&](int buf) {
        const uint32_t st  = sbase + (uint32_t)buf * STAGE;
        const uint32_t sAh = st;
        const uint32_t sAl = st + A_T;
        const uint32_t sBh = st + 2 * A_T;
        const uint32_t sBl = st + 2 * A_T + B_T;
#pragma unroll
        for (int ks = 0; ks < 4; ++ks) {
            uint32_t ah[2][4], al[2][4], b[8][2];
#pragma unroll
            for (int mt = 0; mt < 2; ++mt) {
                const uint32_t row = aRow + mt * 16;
                const uint32_t seg = ((uint32_t)(ks * 2) + aKhi) ^ (row & 7);
                const uint32_t off = row * 128 + (seg << 4);
                ldm_x4(ah[mt][0], ah[mt][1], ah[mt][2], ah[mt][3], sAh + off);
                ldm_x4(al[mt][0], al[mt][1], al[mt][2], al[mt][3], sAl + off);
            }
#pragma unroll
            for (int nb = 0; nb < 4; ++nb) {
                const uint32_t row = bRow + nb * 16;
                const uint32_t seg = ((uint32_t)(ks * 2) + bKhi) ^ (row & 7);
                ldm_x4(b[nb * 2][0], b[nb * 2][1], b[nb * 2 + 1][0], b[nb * 2 + 1][1],
                       sBh + row * 128 + (seg << 4));
            }
#pragma unroll
            for (int mt = 0; mt < 2; ++mt)
#pragma unroll
                for (int nt = 0; nt < 8; ++nt)
                    mma16816(acc[mt][nt], ah[mt], b[nt]);   // Ah*Bh
#pragma unroll
            for (int mt = 0; mt < 2; ++mt)
#pragma unroll
                for (int nt = 0; nt < 8; ++nt)
                    mma16816(acc[mt][nt], al[mt], b[nt]);   // Al*Bh
#pragma unroll
            for (int nb = 0; nb < 4; ++nb) {
                const uint32_t row = bRow + nb * 16;
                const uint32_t seg = ((uint32_t)(ks * 2) + bKhi) ^ (row & 7);
                ldm_x4(b[nb * 2][0], b[nb * 2][1], b[nb * 2 + 1][0], b[nb * 2 + 1][1],
                       sBl + row * 128 + (seg << 4));
            }
#pragma unroll
            for (int mt = 0; mt < 2; ++mt)
#pragma unroll
                for (int nt = 0; nt < 8; ++nt)
                    mma16816(acc[mt][nt], ah[mt], b[nt]);   // Ah*Bl
        }
    };

    load_chunk(0);
    if (nc > 1) load_chunk(1);
    for (int c = 0; c < nc; ++c) {
        if (c + 2 < nc) cp_wait<1>(); else cp_wait<0>();
        __syncthreads();
        compute_chunk(c & 1);
        __syncthreads();
        if (c + 2 < nc) load_chunk(c + 2);
    }

    // ------------------------------ epilogue --------------------------------
    const int rBase = bm + warpM * 32 + (lane >> 2);
    const int cBase = bn + warpN * 64 + (lane & 3) * 2;
#pragma unroll
    for (int mt = 0; mt < 2; ++mt) {
#pragma unroll
        for (int half = 0; half < 2; ++half) {
            const int row = rBase + mt * 16 + half * 8;
#pragma unroll
            for (int nt = 0; nt < 8; ++nt) {
                const int col = cBase + nt * 8;
                const float v0 = acc[mt][nt][half * 2 + 0];
                const float v1 = acc[mt][nt][half * 2 + 1];
                if (EPI == 0) {
                    __nv_bfloat16 hv[2], lv[2];
                    hv[0] = __float2bfloat16(v0);
                    lv[0] = __float2bfloat16(v0 - __bfloat162float(hv[0]));
                    hv[1] = __float2bfloat16(v1);
                    lv[1] = __float2bfloat16(v1 - __bfloat162float(hv[1]));
                    *reinterpret_cast<uint32_t*>(Ch + (size_t)row * ldc + col) =
                        *reinterpret_cast<const uint32_t*>(hv);
                    *reinterpret_cast<uint32_t*>(Cl + (size_t)row * ldc + col) =
                        *reinterpret_cast<const uint32_t*>(lv);
                } else if (EPI == 1) {
                    const int2 m = *reinterpret_cast<const int2*>(
                        Mask + (size_t)bz * sM + (size_t)row * ldc + col);
                    float2 v;
                    v.x = m.x > 0 ? fmaxf(v0, 0.f) : -1e9f;
                    v.y = m.y > 0 ? fmaxf(v1, 0.f) : -1e9f;
                    *reinterpret_cast<float2*>(
                        Cf + (size_t)bz * sC + (size_t)row * ldc + col) = v;
                } else {
                    float2 v; v.x = v0; v.y = v1;
                    *reinterpret_cast<float2*>(
                        Cf + (size_t)bz * sC + (size_t)row * ldc + col) = v;
                }
            }
        }
    }
}

// --------------------------- conversion kernels -----------------------------
__global__ __launch_bounds__(256)
void split_kernel(const float* __restrict__ x, __nv_bfloat16* __restrict__ h,
                  __nv_bfloat16* __restrict__ l, size_t n)
{
    const size_t i = ((size_t)blockIdx.x * blockDim.x + threadIdx.x) * 4;
    if (i >= n) return;
    const float4 v = *reinterpret_cast<const float4*>(x + i);
    __nv_bfloat16 hv[4], lv[4];
    const float vv[4] = {v.x, v.y, v.z, v.w};
#pragma unroll
    for (int j = 0; j < 4; ++j) {
        const __nv_bfloat16 hh = __float2bfloat16(vv[j]);
        hv[j] = hh;
        lv[j] = __float2bfloat16(vv[j] - __bfloat162float(hh));
    }
    *reinterpret_cast<uint2*>(h + i) = *reinterpret_cast<const uint2*>(hv);
    *reinterpret_cast<uint2*>(l + i) = *reinterpret_cast<const uint2*>(lv);
}

// Transpose+split (and optionally direct split) with vectorized stores.
// in: [Bz, R, C]; ht/lt: [Bz, C, R]; (DIRECT) h/l: [Bz, R, C].
template<bool DIRECT>
__global__ __launch_bounds__(256)
void tsplit2_kernel(const float* __restrict__ x,
                    __nv_bfloat16* __restrict__ h, __nv_bfloat16* __restrict__ l,
                    __nv_bfloat16* __restrict__ ht, __nv_bfloat16* __restrict__ lt,
                    int R, int C)
{
    __shared__ float t[64][65];
    const size_t boff = (size_t)blockIdx.z * R * C;
    const int r0 = blockIdx.y * 64, c0 = blockIdx.x * 64;
    const int tid = threadIdx.x;

    const int rr = tid >> 4;
    const int cc = (tid & 15) * 4;
#pragma unroll
    for (int i = 0; i < 4; ++i) {
        const int row = rr + i * 16;
        const float4 v = *reinterpret_cast<const float4*>(
            x + boff + (size_t)(r0 + row) * C + c0 + cc);
        t[row][cc] = v.x; t[row][cc + 1] = v.y;
        t[row][cc + 2] = v.z; t[row][cc + 3] = v.w;
        if (DIRECT) {
            const float vv[4] = {v.x, v.y, v.z, v.w};
            __nv_bfloat16 hv[4], lv[4];
#pragma unroll
            for (int j = 0; j < 4; ++j) {
                hv[j] = __float2bfloat16(vv[j]);
                lv[j] = __float2bfloat16(vv[j] - __bfloat162float(hv[j]));
            }
            const size_t o = boff + (size_t)(r0 + row) * C + c0 + cc;
            *reinterpret_cast<uint2*>(h + o) = *reinterpret_cast<const uint2*>(hv);
            *reinterpret_cast<uint2*>(l + o) = *reinterpret_cast<const uint2*>(lv);
        }
    }
    __syncthreads();

#pragma unroll
    for (int i = 0; i < 2; ++i) {
        const int s = tid + i * 256;
        const int orow = s >> 3;        // input column index
        const int oc = (s & 7) * 8;     // input row index base
        __nv_bfloat16 hv[8], lv[8];
#pragma unroll
        for (int j = 0; j < 8; ++j) {
            const float v = t[oc + j][orow];
            hv[j] = __float2bfloat16(v);
            lv[j] = __float2bfloat16(v - __bfloat162float(hv[j]));
        }
        const size_t o = boff + (size_t)(c0 + orow) * R + r0 + oc;
        *reinterpret_cast<uint4*>(ht + o) = *reinterpret_cast<const uint4*>(hv);
        *reinterpret_cast<uint4*>(lt + o) = *reinterpret_cast<const uint4*>(lv);
    }
}

// softmax in place over rows of length N; also emits split bf16 attn
__global__ __launch_bounds__(256)
void softmax_split_kernel(float* __restrict__ attn, __nv_bfloat16* __restrict__ ah,
                          __nv_bfloat16* __restrict__ al, int N)
{
    const size_t row = blockIdx.x;
    float* p = attn + row * (size_t)N;
    __nv_bfloat16* ph = ah + row * (size_t)N;
    __nv_bfloat16* pl = al + row * (size_t)N;
    const int tid = threadIdx.x;
    __shared__ float red[256];

    float lmax = -3.4e38f;
    for (int i = tid; i < N; i += 256) lmax = fmaxf(lmax, p[i]);
    red[tid] = lmax;
    __syncthreads();
#pragma unroll
    for (int s = 128; s > 0; s >>= 1) {
        if (tid < s) red[tid] = fmaxf(red[tid], red[tid + s]);
        __syncthreads();
    }
    const float rmax = red[0];
    __syncthreads();

    float lsum = 0.f;
    for (int i = tid; i < N; i += 256) {
        const float v = __expf(p[i] - rmax);
        p[i] = v;
        lsum += v;
    }
    red[tid] = lsum;
    __syncthreads();
#pragma unroll
    for (int s = 128; s > 0; s >>= 1) {
        if (tid < s) red[tid] += red[tid + s];
        __syncthreads();
    }
    const float inv = 1.0f / red[0];
    __syncthreads();

    for (int i = tid; i < N; i += 256) {
        const float v = p[i] * inv;
        p[i] = v;
        const __nv_bfloat16 h = __float2bfloat16(v);
        ph[i] = h;
        pl[i] = __float2bfloat16(v - __bfloat162float(h));
    }
}

// --------------------------------- launch -----------------------------------
extern "C" void kernel_launch(void* const* d_in, const int* in_sizes, int n_in,
                              void* d_out, int out_size)
{
    const float* query = (const float*)d_in[0];   // (B, N, H)
    const float* value = (const float*)d_in[1];   // (B, N, H)
    const int*   mask  = (const int*)d_in[2];     // (B, N, N)
    const float* W     = (const float*)d_in[3];   // (H, H)

    float* out  = (float*)d_out;                   // (B, N, H)
    float* attn = out + (size_t)B_ * N_ * H_;      // (B, N, N)

    __nv_bfloat16 *Qh, *Ql, *Wth, *Wtl, *Vh, *Vl, *VTh, *VTl, *Ih, *Il, *ATh, *ATl;
    cudaGetSymbolAddress((void**)&Qh,  g_Qh);
    cudaGetSymbolAddress((void**)&Ql,  g_Ql);
    cudaGetSymbolAddress((void**)&Wth, g_Wth);
    cudaGetSymbolAddress((void**)&Wtl, g_Wtl);
    cudaGetSymbolAddress((void**)&Vh,  g_Vh);
    cudaGetSymbolAddress((void**)&Vl,  g_Vl);
    cudaGetSymbolAddress((void**)&VTh, g_VTh);
    cudaGetSymbolAddress((void**)&VTl, g_VTl);
    cudaGetSymbolAddress((void**)&Ih,  g_Ih);
    cudaGetSymbolAddress((void**)&Il,  g_Il);
    cudaGetSymbolAddress((void**)&ATh, g_ATh);
    cudaGetSymbolAddress((void**)&ATl, g_ATl);

    cudaFuncSetAttribute(gemm_sp<0>, cudaFuncAttributeMaxDynamicSharedMemorySize, SMEM_BYTES);
    cudaFuncSetAttribute(gemm_sp<1>, cudaFuncAttributeMaxDynamicSharedMemorySize, SMEM_BYTES);
    cudaFuncSetAttribute(gemm_sp<2>, cudaFuncAttributeMaxDynamicSharedMemorySize, SMEM_BYTES);

    const size_t nQ = (size_t)B_ * N_ * H_;

    // Split Q; split+transpose V (single read); transpose W.
    split_kernel<<<(unsigned)(nQ / 4 / 256), 256>>>(query, Qh, Ql, nQ);
    tsplit2_kernel<true><<<dim3(H_ / 64, N_ / 64, B_), 256>>>(
        value, Vh, Vl, VTh, VTl, N_, H_);
    tsplit2_kernel<false><<<dim3(H_ / 64, H_ / 64, 1), 256>>>(
        W, nullptr, nullptr, Wth, Wtl, H_, H_);

    // GEMM1: interm = Q @ W -> split bf16   (M=B*N, Ncols=H, K=H)
    gemm_sp<0><<<dim3(H_ / 256, (B_ * N_) / 128, 1), 512, SMEM_BYTES>>>(
        Qh, Ql, Wth, Wtl, nullptr, Ih, Il, nullptr,
        H_, H_, 0, 0, 0, 0);

    // GEMM2: logits = mask>0 ? relu(interm @ V^T) : -1e9  (fp32 into attn)
    gemm_sp<1><<<dim3(N_ / 256, N_ / 128, B_), 512, SMEM_BYTES>>>(
        Ih, Il, Vh, Vl, attn, nullptr, nullptr, mask,
        H_, N_,
        (size_t)N_ * H_, (size_t)N_ * H_, (size_t)N_ * N_, (size_t)N_ * N_);

    // softmax in place + split bf16 attn
    softmax_split_kernel<<<B_ * N_, 256>>>(attn, ATh, ATl, N_);

    // GEMM3: out = attn @ V   (B given as V^T rows: vt[b,h,n], K = N)
    gemm_sp<2><<<dim3(H_ / 256, N_ / 128, B_), 512, SMEM_BYTES>>>(
        ATh, ATl, VTh, VTl, out, nullptr, nullptr, nullptr,
        N_, H_,
        (size_t)N_ * N_, (size_t)H_ * N_, (size_t)N_ * H_, 0);
}

// round 5
// speedup vs baseline: 3.1448x; 1.0458x over previous
#include <cuda_runtime.h>
#include <cuda_bf16.h>
#include <cstdint>

// ---------------------------------------------------------------------------
// BilinearAttention via mma.sync (HMMA) split-bf16, sm_103-safe PTX only.
// Split GEMM: C = Ah*Bh + Al*Bh + Ah*Bl, tiles loaded once per K-chunk.
// CTA tile 128x128, BK=32, 256 threads, 3-stage cp.async, 2 CTAs/SM.
// ---------------------------------------------------------------------------

#define B_   8
#define N_   2048
#define H_   1024

// ------------------------- scratch (no allocations) -------------------------
__device__ __nv_bfloat16 g_Qh[(size_t)B_ * N_ * H_];
__device__ __nv_bfloat16 g_Ql[(size_t)B_ * N_ * H_];
__device__ __nv_bfloat16 g_Wth[(size_t)H_ * H_];
__device__ __nv_bfloat16 g_Wtl[(size_t)H_ * H_];
__device__ __nv_bfloat16 g_Vh[(size_t)B_ * N_ * H_];
__device__ __nv_bfloat16 g_Vl[(size_t)B_ * N_ * H_];
__device__ __nv_bfloat16 g_VTh[(size_t)B_ * H_ * N_];
__device__ __nv_bfloat16 g_VTl[(size_t)B_ * H_ * N_];
__device__ __nv_bfloat16 g_Ih[(size_t)B_ * N_ * H_];
__device__ __nv_bfloat16 g_Il[(size_t)B_ * N_ * H_];
__device__ __nv_bfloat16 g_ATh[(size_t)B_ * N_ * N_];
__device__ __nv_bfloat16 g_ATl[(size_t)B_ * N_ * N_];

// ----------------------------- PTX primitives -------------------------------
__device__ __forceinline__ uint32_t smem_u32(const void* p) {
    uint32_t a;
    asm("{ .reg .u64 t; cvta.to.shared.u64 t, %1; cvt.u32.u64 %0, t; }"
        : "=r"(a) : "l"(p));
    return a;
}
__device__ __forceinline__ void cp16(uint32_t dst, const void* src) {
    asm volatile("cp.async.cg.shared.global [%0], [%1], 16;" :: "r"(dst), "l"(src));
}
__device__ __forceinline__ void cp_commit() {
    asm volatile("cp.async.commit_group;" ::: "memory");
}
template<int Nn>
__device__ __forceinline__ void cp_wait() {
    asm volatile("cp.async.wait_group %0;" :: "n"(Nn) : "memory");
}
__device__ __forceinline__ void ldm_x4(uint32_t& r0, uint32_t& r1, uint32_t& r2,
                                       uint32_t& r3, uint32_t addr) {
    asm volatile("ldmatrix.sync.aligned.m8n8.x4.shared.b16 {%0,%1,%2,%3}, [%4];"
                 : "=r"(r0), "=r"(r1), "=r"(r2), "=r"(r3) : "r"(addr));
}
__device__ __forceinline__ void mma16816(float* c, const uint32_t* a, const uint32_t* b) {
    asm volatile(
        "mma.sync.aligned.m16n8k16.row.col.f32.bf16.bf16.f32 "
        "{%0,%1,%2,%3}, {%4,%5,%6,%7}, {%8,%9}, {%0,%1,%2,%3};"
        : "+f"(c[0]), "+f"(c[1]), "+f"(c[2]), "+f"(c[3])
        : "r"(a[0]), "r"(a[1]), "r"(a[2]), "r"(a[3]), "r"(b[0]), "r"(b[1]));
}

// ---------------------- split-bf16 tensor-core GEMM --------------------------
// CTA tile 128(M) x 128(N), BK=32. 8 warps, warp tile 32x64.
// Stage: Ah(8K) Al(8K) Bh(8K) Bl(8K) = 32KB; 3 stages = 96KB; 2 CTAs/SM.
#define A_T   8192
#define STAGE (4 * A_T)
#define SMEM_BYTES (3 * STAGE)

template<int EPI>  // 0: split bf16 hi/lo; 1: mask+relu fp32; 2: plain fp32
__global__ __launch_bounds__(256, 2)
void gemm_sp(const __nv_bfloat16* __restrict__ Ah, const __nv_bfloat16* __restrict__ Al,
             const __nv_bfloat16* __restrict__ Bh, const __nv_bfloat16* __restrict__ Bl,
             float* __restrict__ Cf,
             __nv_bfloat16* __restrict__ Ch, __nv_bfloat16* __restrict__ Cl,
             const int* __restrict__ Mask,
             int K, int ldc,
             size_t sA, size_t sB, size_t sC, size_t sM)
{
    extern __shared__ __align__(1024) char smem[];
    const uint32_t sbase = smem_u32(smem);
    const int tid  = threadIdx.x;
    const int wid  = tid >> 5;
    const int lane = tid & 31;
    const int bm = blockIdx.y * 128;
    const int bn = blockIdx.x * 128;
    const int bz = blockIdx.z;

    Ah += (size_t)bz * sA;  Al += (size_t)bz * sA;
    Bh += (size_t)bz * sB;  Bl += (size_t)bz * sB;

    const int warpM = wid >> 1;    // 0..3 -> *32
    const int warpN = wid & 1;     // 0..1 -> *64
    const int nc = K >> 5;

    float acc[2][8][4];
#pragma unroll
    for (int i = 0; i < 2; i++)
#pragma unroll
        for (int j = 0; j < 8; j++)
#pragma unroll
            for (int q = 0; q < 4; q++) acc[i][j][q] = 0.f;

    // loader mapping: 512 16B-segs per tile (128 rows x 4 segs); 2 per thread
    auto load_chunk = [&](int c) {
        const int kk = c << 5;
        const uint32_t st = sbase + (uint32_t)(c % 3) * STAGE;
#pragma unroll
        for (int i = 0; i < 2; ++i) {
            const int s = tid + i * 256;
            const int row = s >> 2, col = s & 3;
            const uint32_t off =
                (uint32_t)row * 64 + ((uint32_t)(col ^ ((row >> 1) & 3)) << 4);
            const size_t ga = (size_t)(bm + row) * K + kk + col * 8;
            const size_t gb = (size_t)(bn + row) * K + kk + col * 8;
            cp16(st + off, Ah + ga);
            cp16(st + A_T + off, Al + ga);
            cp16(st + 2 * A_T + off, Bh + gb);
            cp16(st + 3 * A_T + off, Bl + gb);
        }
        cp_commit();
    };

    const uint32_t aRow = (uint32_t)(warpM * 32 + (lane & 15));
    const uint32_t aKhi = (uint32_t)(lane >> 4);
    const uint32_t bRow = (uint32_t)(warpN * 64 + ((lane & 16) >> 1) + (lane & 7));
    const uint32_t bKhi = (uint32_t)((lane >> 3) & 1);

    auto compute_chunk = [&](int buf) {
        const uint32_t st  = sbase + (uint32_t)buf * STAGE;
        const uint32_t sAh = st;
        const uint32_t sAl = st + A_T;
        const uint32_t sBh = st + 2 * A_T;
        const uint32_t sBl = st + 3 * A_T;
#pragma unroll
        for (int ks = 0; ks < 2; ++ks) {
            uint32_t ah[2][4], al[2][4], b[8][2];
#pragma unroll
            for (int mt = 0; mt < 2; ++mt) {
                const uint32_t row = aRow + mt * 16;
                const uint32_t seg = ((uint32_t)(ks * 2) + aKhi) ^ ((row >> 1) & 3);
                const uint32_t off = row * 64 + (seg << 4);
                ldm_x4(ah[mt][0], ah[mt][1], ah[mt][2], ah[mt][3], sAh + off);
                ldm_x4(al[mt][0], al[mt][1], al[mt][2], al[mt][3], sAl + off);
            }
#pragma unroll
            for (int nb = 0; nb < 4; ++nb) {
                const uint32_t row = bRow + nb * 16;
                const uint32_t seg = ((uint32_t)(ks * 2) + bKhi) ^ ((row >> 1) & 3);
                ldm_x4(b[nb * 2][0], b[nb * 2][1], b[nb * 2 + 1][0], b[nb * 2 + 1][1],
                       sBh + row * 64 + (seg << 4));
            }
#pragma unroll
            for (int mt = 0; mt < 2; ++mt)
#pragma unroll
                for (int nt = 0; nt < 8; ++nt)
                    mma16816(acc[mt][nt], ah[mt], b[nt]);   // Ah*Bh
#pragma unroll
            for (int mt = 0; mt < 2; ++mt)
#pragma unroll
                for (int nt = 0; nt < 8; ++nt)
                    mma16816(acc[mt][nt], al[mt], b[nt]);   // Al*Bh
#pragma unroll
            for (int nb = 0; nb < 4; ++nb) {
                const uint32_t row = bRow + nb * 16;
                const uint32_t seg = ((uint32_t)(ks * 2) + bKhi) ^ ((row >> 1) & 3);
                ldm_x4(b[nb * 2][0], b[nb * 2][1], b[nb * 2 + 1][0], b[nb * 2 + 1][1],
                       sBl + row * 64 + (seg << 4));
            }
#pragma unroll
            for (int mt = 0; mt < 2; ++mt)
#pragma unroll
                for (int nt = 0; nt < 8; ++nt)
                    mma16816(acc[mt][nt], ah[mt], b[nt]);   // Ah*Bl
        }
    };

    load_chunk(0);
    load_chunk(1);
    for (int c = 0; c < nc; ++c) {
        if (c + 1 < nc) cp_wait<1>(); else cp_wait<0>();
        __syncthreads();
        if (c + 2 < nc) load_chunk(c + 2);   // slot (c-1)%3: safe after barrier
        compute_chunk(c % 3);
    }

    // ------------------------------ epilogue --------------------------------
    const int rBase = bm + warpM * 32 + (lane >> 2);
    const int cBase = bn + warpN * 64 + (lane & 3) * 2;
#pragma unroll
    for (int mt = 0; mt < 2; ++mt) {
#pragma unroll
        for (int half = 0; half < 2; ++half) {
            const int row = rBase + mt * 16 + half * 8;
#pragma unroll
            for (int nt = 0; nt < 8; ++nt) {
                const int col = cBase + nt * 8;
                const float v0 = acc[mt][nt][half * 2 + 0];
                const float v1 = acc[mt][nt][half * 2 + 1];
                if (EPI == 0) {
                    __nv_bfloat16 hv[2], lv[2];
                    hv[0] = __float2bfloat16(v0);
                    lv[0] = __float2bfloat16(v0 - __bfloat162float(hv[0]));
                    hv[1] = __float2bfloat16(v1);
                    lv[1] = __float2bfloat16(v1 - __bfloat162float(hv[1]));
                    *reinterpret_cast<uint32_t*>(Ch + (size_t)row * ldc + col) =
                        *reinterpret_cast<const uint32_t*>(hv);
                    *reinterpret_cast<uint32_t*>(Cl + (size_t)row * ldc + col) =
                        *reinterpret_cast<const uint32_t*>(lv);
                } else if (EPI == 1) {
                    const int2 m = *reinterpret_cast<const int2*>(
                        Mask + (size_t)bz * sM + (size_t)row * ldc + col);
                    float2 v;
                    v.x = m.x > 0 ? fmaxf(v0, 0.f) : -1e9f;
                    v.y = m.y > 0 ? fmaxf(v1, 0.f) : -1e9f;
                    *reinterpret_cast<float2*>(
                        Cf + (size_t)bz * sC + (size_t)row * ldc + col) = v;
                } else {
                    float2 v; v.x = v0; v.y = v1;
                    *reinterpret_cast<float2*>(
                        Cf + (size_t)bz * sC + (size_t)row * ldc + col) = v;
                }
            }
        }
    }
}

// --------------------------- conversion kernels -----------------------------
__global__ __launch_bounds__(256)
void split_kernel(const float* __restrict__ x, __nv_bfloat16* __restrict__ h,
                  __nv_bfloat16* __restrict__ l, size_t n)
{
    const size_t i = ((size_t)blockIdx.x * blockDim.x + threadIdx.x) * 4;
    if (i >= n) return;
    const float4 v = *reinterpret_cast<const float4*>(x + i);
    __nv_bfloat16 hv[4], lv[4];
    const float vv[4] = {v.x, v.y, v.z, v.w};
#pragma unroll
    for (int j = 0; j < 4; ++j) {
        const __nv_bfloat16 hh = __float2bfloat16(vv[j]);
        hv[j] = hh;
        lv[j] = __float2bfloat16(vv[j] - __bfloat162float(hh));
    }
    *reinterpret_cast<uint2*>(h + i) = *reinterpret_cast<const uint2*>(hv);
    *reinterpret_cast<uint2*>(l + i) = *reinterpret_cast<const uint2*>(lv);
}

// Transpose+split (and optionally direct split) with vectorized stores.
template<bool DIRECT>
__global__ __launch_bounds__(256)
void tsplit2_kernel(const float* __restrict__ x,
                    __nv_bfloat16* __restrict__ h, __nv_bfloat16* __restrict__ l,
                    __nv_bfloat16* __restrict__ ht, __nv_bfloat16* __restrict__ lt,
                    int R, int C)
{
    __shared__ float t[64][65];
    const size_t boff = (size_t)blockIdx.z * R * C;
    const int r0 = blockIdx.y * 64, c0 = blockIdx.x * 64;
    const int tid = threadIdx.x;

    const int rr = tid >> 4;
    const int cc = (tid & 15) * 4;
#pragma unroll
    for (int i = 0; i < 4; ++i) {
        const int row = rr + i * 16;
        const float4 v = *reinterpret_cast<const float4*>(
            x + boff + (size_t)(r0 + row) * C + c0 + cc);
        t[row][cc] = v.x; t[row][cc + 1] = v.y;
        t[row][cc + 2] = v.z; t[row][cc + 3] = v.w;
        if (DIRECT) {
            const float vv[4] = {v.x, v.y, v.z, v.w};
            __nv_bfloat16 hv[4], lv[4];
#pragma unroll
            for (int j = 0; j < 4; ++j) {
                hv[j] = __float2bfloat16(vv[j]);
                lv[j] = __float2bfloat16(vv[j] - __bfloat162float(hv[j]));
            }
            const size_t o = boff + (size_t)(r0 + row) * C + c0 + cc;
            *reinterpret_cast<uint2*>(h + o) = *reinterpret_cast<const uint2*>(hv);
            *reinterpret_cast<uint2*>(l + o) = *reinterpret_cast<const uint2*>(lv);
        }
    }
    __syncthreads();

#pragma unroll
    for (int i = 0; i < 2; ++i) {
        const int s = tid + i * 256;
        const int orow = s >> 3;
        const int oc = (s & 7) * 8;
        __nv_bfloat16 hv[8], lv[8];
#pragma unroll
        for (int j = 0; j < 8; ++j) {
            const float v = t[oc + j][orow];
            hv[j] = __float2bfloat16(v);
            lv[j] = __float2bfloat16(v - __bfloat162float(hv[j]));
        }
        const size_t o = boff + (size_t)(c0 + orow) * R + r0 + oc;
        *reinterpret_cast<uint4*>(ht + o) = *reinterpret_cast<const uint4*>(hv);
        *reinterpret_cast<uint4*>(lt + o) = *reinterpret_cast<const uint4*>(lv);
    }
}

// softmax in place over rows of length N; also emits split bf16 attn
__global__ __launch_bounds__(256)
void softmax_split_kernel(float* __restrict__ attn, __nv_bfloat16* __restrict__ ah,
                          __nv_bfloat16* __restrict__ al, int N)
{
    const size_t row = blockIdx.x;
    float* p = attn + row * (size_t)N;
    __nv_bfloat16* ph = ah + row * (size_t)N;
    __nv_bfloat16* pl = al + row * (size_t)N;
    const int tid = threadIdx.x;
    __shared__ float red[256];

    float lmax = -3.4e38f;
    for (int i = tid; i < N; i += 256) lmax = fmaxf(lmax, p[i]);
    red[tid] = lmax;
    __syncthreads();
#pragma unroll
    for (int s = 128; s > 0; s >>= 1) {
        if (tid < s) red[tid] = fmaxf(red[tid], red[tid + s]);
        __syncthreads();
    }
    const float rmax = red[0];
    __syncthreads();

    float lsum = 0.f;
    for (int i = tid; i < N; i += 256) {
        const float v = __expf(p[i] - rmax);
        p[i] = v;
        lsum += v;
    }
    red[tid] = lsum;
    __syncthreads();
#pragma unroll
    for (int s = 128; s > 0; s >>= 1) {
        if (tid < s) red[tid] += red[tid + s];
        __syncthreads();
    }
    const float inv = 1.0f / red[0];
    __syncthreads();

    for (int i = tid; i < N; i += 256) {
        const float v = p[i] * inv;
        p[i] = v;
        const __nv_bfloat16 h = __float2bfloat16(v);
        ph[i] = h;
        pl[i] = __float2bfloat16(v - __bfloat162float(h));
    }
}

// --------------------------------- launch -----------------------------------
extern "C" void kernel_launch(void* const* d_in, const int* in_sizes, int n_in,
                              void* d_out, int out_size)
{
    const float* query = (const float*)d_in[0];   // (B, N, H)
    const float* value = (const float*)d_in[1];   // (B, N, H)
    const int*   mask  = (const int*)d_in[2];     // (B, N, N)
    const float* W     = (const float*)d_in[3];   // (H, H)

    float* out  = (float*)d_out;                   // (B, N, H)
    float* attn = out + (size_t)B_ * N_ * H_;      // (B, N, N)

    __nv_bfloat16 *Qh, *Ql, *Wth, *Wtl, *Vh, *Vl, *VTh, *VTl, *Ih, *Il, *ATh, *ATl;
    cudaGetSymbolAddress((void**)&Qh,  g_Qh);
    cudaGetSymbolAddress((void**)&Ql,  g_Ql);
    cudaGetSymbolAddress((void**)&Wth, g_Wth);
    cudaGetSymbolAddress((void**)&Wtl, g_Wtl);
    cudaGetSymbolAddress((void**)&Vh,  g_Vh);
    cudaGetSymbolAddress((void**)&Vl,  g_Vl);
    cudaGetSymbolAddress((void**)&VTh, g_VTh);
    cudaGetSymbolAddress((void**)&VTl, g_VTl);
    cudaGetSymbolAddress((void**)&Ih,  g_Ih);
    cudaGetSymbolAddress((void**)&Il,  g_Il);
    cudaGetSymbolAddress((void**)&ATh, g_ATh);
    cudaGetSymbolAddress((void**)&ATl, g_ATl);

    cudaFuncSetAttribute(gemm_sp<0>, cudaFuncAttributeMaxDynamicSharedMemorySize, SMEM_BYTES);
    cudaFuncSetAttribute(gemm_sp<1>, cudaFuncAttributeMaxDynamicSharedMemorySize, SMEM_BYTES);
    cudaFuncSetAttribute(gemm_sp<2>, cudaFuncAttributeMaxDynamicSharedMemorySize, SMEM_BYTES);

    const size_t nQ = (size_t)B_ * N_ * H_;

    // Split Q; split+transpose V (single read); transpose W.
    split_kernel<<<(unsigned)(nQ / 4 / 256), 256>>>(query, Qh, Ql, nQ);
    tsplit2_kernel<true><<<dim3(H_ / 64, N_ / 64, B_), 256>>>(
        value, Vh, Vl, VTh, VTl, N_, H_);
    tsplit2_kernel<false><<<dim3(H_ / 64, H_ / 64, 1), 256>>>(
        W, nullptr, nullptr, Wth, Wtl, H_, H_);

    // GEMM1: interm = Q @ W -> split bf16   (M=B*N, Ncols=H, K=H)
    gemm_sp<0><<<dim3(H_ / 128, (B_ * N_) / 128, 1), 256, SMEM_BYTES>>>(
        Qh, Ql, Wth, Wtl, nullptr, Ih, Il, nullptr,
        H_, H_, 0, 0, 0, 0);

    // GEMM2: logits = mask>0 ? relu(interm @ V^T) : -1e9  (fp32 into attn)
    gemm_sp<1><<<dim3(N_ / 128, N_ / 128, B_), 256, SMEM_BYTES>>>(
        Ih, Il, Vh, Vl, attn, nullptr, nullptr, mask,
        H_, N_,
        (size_t)N_ * H_, (size_t)N_ * H_, (size_t)N_ * N_, (size_t)N_ * N_);

    // softmax in place + split bf16 attn
    softmax_split_kernel<<<B_ * N_, 256>>>(attn, ATh, ATl, N_);

    // GEMM3: out = attn @ V   (B given as V^T rows: vt[b,h,n], K = N)
    gemm_sp<2><<<dim3(H_ / 128, N_ / 128, B_), 256, SMEM_BYTES>>>(
        ATh, ATl, VTh, VTl, out, nullptr, nullptr, nullptr,
        N_, H_,
        (size_t)N_ * N_, (size_t)H_ * N_, (size_t)N_ * H_, 0);
}

// round 6
// speedup vs baseline: 4.6724x; 1.4857x over previous
#include <cuda_runtime.h>
#include <cuda_bf16.h>
#include <cstdint>

// ---------------------------------------------------------------------------
// BilinearAttention, split-bf16 HMMA + sparse softmax-gather output.
//   interm = Q @ W                 GEMM1 (split-bf16 epilogue)
//   logits = mask/relu(interm@V^T) GEMM2 (mask+relu epilogue, fp32)
//   attn   = softmax(logits)       attn rows are (near) one-hot in fp32:
//   out    = attn @ V              == weighted gather of the few significant
//                                     rows of V -- fused into softmax kernel.
// Output buffer: [ out (B*N*H) | attn (B*N*N) ]
// ---------------------------------------------------------------------------

#define B_   8
#define N_   2048
#define H_   1024

// ------------------------- scratch (no allocations) -------------------------
__device__ __nv_bfloat16 g_Qh[(size_t)B_ * N_ * H_];
__device__ __nv_bfloat16 g_Ql[(size_t)B_ * N_ * H_];
__device__ __nv_bfloat16 g_Wth[(size_t)H_ * H_];
__device__ __nv_bfloat16 g_Wtl[(size_t)H_ * H_];
__device__ __nv_bfloat16 g_Vh[(size_t)B_ * N_ * H_];
__device__ __nv_bfloat16 g_Vl[(size_t)B_ * N_ * H_];
__device__ __nv_bfloat16 g_Ih[(size_t)B_ * N_ * H_];
__device__ __nv_bfloat16 g_Il[(size_t)B_ * N_ * H_];

// ----------------------------- PTX primitives -------------------------------
__device__ __forceinline__ uint32_t smem_u32(const void* p) {
    uint32_t a;
    asm("{ .reg .u64 t; cvta.to.shared.u64 t, %1; cvt.u32.u64 %0, t; }"
        : "=r"(a) : "l"(p));
    return a;
}
__device__ __forceinline__ void cp16(uint32_t dst, const void* src) {
    asm volatile("cp.async.cg.shared.global [%0], [%1], 16;" :: "r"(dst), "l"(src));
}
__device__ __forceinline__ void cp_commit() {
    asm volatile("cp.async.commit_group;" ::: "memory");
}
template<int Nn>
__device__ __forceinline__ void cp_wait() {
    asm volatile("cp.async.wait_group %0;" :: "n"(Nn) : "memory");
}
__device__ __forceinline__ void ldm_x4(uint32_t& r0, uint32_t& r1, uint32_t& r2,
                                       uint32_t& r3, uint32_t addr) {
    asm volatile("ldmatrix.sync.aligned.m8n8.x4.shared.b16 {%0,%1,%2,%3}, [%4];"
                 : "=r"(r0), "=r"(r1), "=r"(r2), "=r"(r3) : "r"(addr));
}
__device__ __forceinline__ void mma16816(float* c, const uint32_t* a, const uint32_t* b) {
    asm volatile(
        "mma.sync.aligned.m16n8k16.row.col.f32.bf16.bf16.f32 "
        "{%0,%1,%2,%3}, {%4,%5,%6,%7}, {%8,%9}, {%0,%1,%2,%3};"
        : "+f"(c[0]), "+f"(c[1]), "+f"(c[2]), "+f"(c[3])
        : "r"(a[0]), "r"(a[1]), "r"(a[2]), "r"(a[3]), "r"(b[0]), "r"(b[1]));
}

// ---------------------- split-bf16 tensor-core GEMM --------------------------
// CTA tile 128(M) x 128(N), BK=32. 8 warps, warp tile 32x64.
// Stage 32KB; 3 stages = 96KB; 2 CTAs/SM.
#define A_T   8192
#define STAGE (4 * A_T)
#define SMEM_BYTES (3 * STAGE)

template<int EPI>  // 0: split bf16 hi/lo; 1: mask+relu fp32
__global__ __launch_bounds__(256, 2)
void gemm_sp(const __nv_bfloat16* __restrict__ Ah, const __nv_bfloat16* __restrict__ Al,
             const __nv_bfloat16* __restrict__ Bh, const __nv_bfloat16* __restrict__ Bl,
             float* __restrict__ Cf,
             __nv_bfloat16* __restrict__ Ch, __nv_bfloat16* __restrict__ Cl,
             const int* __restrict__ Mask,
             int K, int ldc,
             size_t sA, size_t sB, size_t sC, size_t sM)
{
    extern __shared__ __align__(1024) char smem[];
    const uint32_t sbase = smem_u32(smem);
    const int tid  = threadIdx.x;
    const int wid  = tid >> 5;
    const int lane = tid & 31;
    const int bm = blockIdx.y * 128;
    const int bn = blockIdx.x * 128;
    const int bz = blockIdx.z;

    Ah += (size_t)bz * sA;  Al += (size_t)bz * sA;
    Bh += (size_t)bz * sB;  Bl += (size_t)bz * sB;

    const int warpM = wid >> 1;
    const int warpN = wid & 1;
    const int nc = K >> 5;

    float acc[2][8][4];
#pragma unroll
    for (int i = 0; i < 2; i++)
#pragma unroll
        for (int j = 0; j < 8; j++)
#pragma unroll
            for (int q = 0; q < 4; q++) acc[i][j][q] = 0.f;

    auto load_chunk = [&](int c) {
        const int kk = c << 5;
        const uint32_t st = sbase + (uint32_t)(c % 3) * STAGE;
#pragma unroll
        for (int i = 0; i < 2; ++i) {
            const int s = tid + i * 256;
            const int row = s >> 2, col = s & 3;
            const uint32_t off =
                (uint32_t)row * 64 + ((uint32_t)(col ^ ((row >> 1) & 3)) << 4);
            const size_t ga = (size_t)(bm + row) * K + kk + col * 8;
            const size_t gb = (size_t)(bn + row) * K + kk + col * 8;
            cp16(st + off, Ah + ga);
            cp16(st + A_T + off, Al + ga);
            cp16(st + 2 * A_T + off, Bh + gb);
            cp16(st + 3 * A_T + off, Bl + gb);
        }
        cp_commit();
    };

    const uint32_t aRow = (uint32_t)(warpM * 32 + (lane & 15));
    const uint32_t aKhi = (uint32_t)(lane >> 4);
    const uint32_t bRow = (uint32_t)(warpN * 64 + ((lane & 16) >> 1) + (lane & 7));
    const uint32_t bKhi = (uint32_t)((lane >> 3) & 1);

    auto compute_chunk = [&](int buf) {
        const uint32_t st  = sbase + (uint32_t)buf * STAGE;
        const uint32_t sAh = st;
        const uint32_t sAl = st + A_T;
        const uint32_t sBh = st + 2 * A_T;
        const uint32_t sBl = st + 3 * A_T;
#pragma unroll
        for (int ks = 0; ks < 2; ++ks) {
            uint32_t ah[2][4], al[2][4], b[8][2];
#pragma unroll
            for (int mt = 0; mt < 2; ++mt) {
                const uint32_t row = aRow + mt * 16;
                const uint32_t seg = ((uint32_t)(ks * 2) + aKhi) ^ ((row >> 1) & 3);
                const uint32_t off = row * 64 + (seg << 4);
                ldm_x4(ah[mt][0], ah[mt][1], ah[mt][2], ah[mt][3], sAh + off);
                ldm_x4(al[mt][0], al[mt][1], al[mt][2], al[mt][3], sAl + off);
            }
#pragma unroll
            for (int nb = 0; nb < 4; ++nb) {
                const uint32_t row = bRow + nb * 16;
                const uint32_t seg = ((uint32_t)(ks * 2) + bKhi) ^ ((row >> 1) & 3);
                ldm_x4(b[nb * 2][0], b[nb * 2][1], b[nb * 2 + 1][0], b[nb * 2 + 1][1],
                       sBh + row * 64 + (seg << 4));
            }
#pragma unroll
            for (int mt = 0; mt < 2; ++mt)
#pragma unroll
                for (int nt = 0; nt < 8; ++nt)
                    mma16816(acc[mt][nt], ah[mt], b[nt]);   // Ah*Bh
#pragma unroll
            for (int mt = 0; mt < 2; ++mt)
#pragma unroll
                for (int nt = 0; nt < 8; ++nt)
                    mma16816(acc[mt][nt], al[mt], b[nt]);   // Al*Bh
#pragma unroll
            for (int nb = 0; nb < 4; ++nb) {
                const uint32_t row = bRow + nb * 16;
                const uint32_t seg = ((uint32_t)(ks * 2) + bKhi) ^ ((row >> 1) & 3);
                ldm_x4(b[nb * 2][0], b[nb * 2][1], b[nb * 2 + 1][0], b[nb * 2 + 1][1],
                       sBl + row * 64 + (seg << 4));
            }
#pragma unroll
            for (int mt = 0; mt < 2; ++mt)
#pragma unroll
                for (int nt = 0; nt < 8; ++nt)
                    mma16816(acc[mt][nt], ah[mt], b[nt]);   // Ah*Bl
        }
    };

    load_chunk(0);
    load_chunk(1);
    for (int c = 0; c < nc; ++c) {
        if (c + 1 < nc) cp_wait<1>(); else cp_wait<0>();
        __syncthreads();
        if (c + 2 < nc) load_chunk(c + 2);
        compute_chunk(c % 3);
    }

    // ------------------------------ epilogue --------------------------------
    const int rBase = bm + warpM * 32 + (lane >> 2);
    const int cBase = bn + warpN * 64 + (lane & 3) * 2;
#pragma unroll
    for (int mt = 0; mt < 2; ++mt) {
#pragma unroll
        for (int half = 0; half < 2; ++half) {
            const int row = rBase + mt * 16 + half * 8;
#pragma unroll
            for (int nt = 0; nt < 8; ++nt) {
                const int col = cBase + nt * 8;
                const float v0 = acc[mt][nt][half * 2 + 0];
                const float v1 = acc[mt][nt][half * 2 + 1];
                if (EPI == 0) {
                    __nv_bfloat16 hv[2], lv[2];
                    hv[0] = __float2bfloat16(v0);
                    lv[0] = __float2bfloat16(v0 - __bfloat162float(hv[0]));
                    hv[1] = __float2bfloat16(v1);
                    lv[1] = __float2bfloat16(v1 - __bfloat162float(hv[1]));
                    *reinterpret_cast<uint32_t*>(Ch + (size_t)row * ldc + col) =
                        *reinterpret_cast<const uint32_t*>(hv);
                    *reinterpret_cast<uint32_t*>(Cl + (size_t)row * ldc + col) =
                        *reinterpret_cast<const uint32_t*>(lv);
                } else {
                    const int2 m = *reinterpret_cast<const int2*>(
                        Mask + (size_t)bz * sM + (size_t)row * ldc + col);
                    float2 v;
                    v.x = m.x > 0 ? fmaxf(v0, 0.f) : -1e9f;
                    v.y = m.y > 0 ? fmaxf(v1, 0.f) : -1e9f;
                    *reinterpret_cast<float2*>(
                        Cf + (size_t)bz * sC + (size_t)row * ldc + col) = v;
                }
            }
        }
    }
}

// --------------------------- conversion kernels -----------------------------
__global__ __launch_bounds__(256)
void split_kernel(const float* __restrict__ x, __nv_bfloat16* __restrict__ h,
                  __nv_bfloat16* __restrict__ l, size_t n)
{
    const size_t i = ((size_t)blockIdx.x * blockDim.x + threadIdx.x) * 4;
    if (i >= n) return;
    const float4 v = *reinterpret_cast<const float4*>(x + i);
    __nv_bfloat16 hv[4], lv[4];
    const float vv[4] = {v.x, v.y, v.z, v.w};
#pragma unroll
    for (int j = 0; j < 4; ++j) {
        const __nv_bfloat16 hh = __float2bfloat16(vv[j]);
        hv[j] = hh;
        lv[j] = __float2bfloat16(vv[j] - __bfloat162float(hh));
    }
    *reinterpret_cast<uint2*>(h + i) = *reinterpret_cast<const uint2*>(hv);
    *reinterpret_cast<uint2*>(l + i) = *reinterpret_cast<const uint2*>(lv);
}

// Transpose+split: in [R,C] -> ht/lt [C,R]
__global__ __launch_bounds__(256)
void tsplit_kernel(const float* __restrict__ x,
                   __nv_bfloat16* __restrict__ ht, __nv_bfloat16* __restrict__ lt,
                   int R, int C)
{
    __shared__ float t[64][65];
    const int r0 = blockIdx.y * 64, c0 = blockIdx.x * 64;
    const int tid = threadIdx.x;

    const int rr = tid >> 4;
    const int cc = (tid & 15) * 4;
#pragma unroll
    for (int i = 0; i < 4; ++i) {
        const int row = rr + i * 16;
        const float4 v = *reinterpret_cast<const float4*>(
            x + (size_t)(r0 + row) * C + c0 + cc);
        t[row][cc] = v.x; t[row][cc + 1] = v.y;
        t[row][cc + 2] = v.z; t[row][cc + 3] = v.w;
    }
    __syncthreads();

#pragma unroll
    for (int i = 0; i < 2; ++i) {
        const int s = tid + i * 256;
        const int orow = s >> 3;
        const int oc = (s & 7) * 8;
        __nv_bfloat16 hv[8], lv[8];
#pragma unroll
        for (int j = 0; j < 8; ++j) {
            const float v = t[oc + j][orow];
            hv[j] = __float2bfloat16(v);
            lv[j] = __float2bfloat16(v - __bfloat162float(hv[j]));
        }
        const size_t o = (size_t)(c0 + orow) * R + r0 + oc;
        *reinterpret_cast<uint4*>(ht + o) = *reinterpret_cast<const uint4*>(hv);
        *reinterpret_cast<uint4*>(lt + o) = *reinterpret_cast<const uint4*>(lv);
    }
}

// ------------------ fused softmax + sparse-gather output --------------------
// One block per attention row. Softmax in place; then out[row] = sum over
// significant entries w_i * V[i,:] (fp32 exact). attn rows are near one-hot,
// so typically 1-3 gather terms; full fallback loop keeps it correct always.
#define SIG_CAP 512
__global__ __launch_bounds__(256)
void softmax_out_kernel(float* __restrict__ attn, const float* __restrict__ V,
                        float* __restrict__ out)
{
    const int rowg = blockIdx.x;           // 0 .. B*N-1
    const int bz   = rowg >> 11;           // / N_
    float* p = attn + (size_t)rowg * N_;
    const float* Vb = V + (size_t)bz * N_ * H_;
    const int tid = threadIdx.x;

    __shared__ float red[256];
    __shared__ int   idxs[SIG_CAP];
    __shared__ float wts[SIG_CAP];
    __shared__ int   cnt;
    if (tid == 0) cnt = 0;

    float lmax = -3.4e38f;
    for (int i = tid; i < N_; i += 256) lmax = fmaxf(lmax, p[i]);
    red[tid] = lmax;
    __syncthreads();
#pragma unroll
    for (int s = 128; s > 0; s >>= 1) {
        if (tid < s) red[tid] = fmaxf(red[tid], red[tid + s]);
        __syncthreads();
    }
    const float rmax = red[0];
    __syncthreads();

    float lsum = 0.f;
    for (int i = tid; i < N_; i += 256) {
        const float v = __expf(p[i] - rmax);
        p[i] = v;
        lsum += v;
    }
    red[tid] = lsum;
    __syncthreads();
#pragma unroll
    for (int s = 128; s > 0; s >>= 1) {
        if (tid < s) red[tid] += red[tid + s];
        __syncthreads();
    }
    const float inv = 1.0f / red[0];
    __syncthreads();

    for (int i = tid; i < N_; i += 256) {
        const float w = p[i] * inv;
        p[i] = w;
        if (w > 1e-9f) {
            const int s = atomicAdd(&cnt, 1);
            if (s < SIG_CAP) { idxs[s] = i; wts[s] = w; }
        }
    }
    __syncthreads();

    // gather: each thread owns 4 contiguous output columns
    const int col = tid * 4;
    float4 acc = make_float4(0.f, 0.f, 0.f, 0.f);
    const int n = cnt;
    if (n <= SIG_CAP) {
        for (int s = 0; s < n; ++s) {
            const float w = wts[s];
            const float4 v = *reinterpret_cast<const float4*>(
                Vb + (size_t)idxs[s] * H_ + col);
            acc.x += w * v.x; acc.y += w * v.y;
            acc.z += w * v.z; acc.w += w * v.w;
        }
    } else {
        for (int i = 0; i < N_; ++i) {
            const float w = p[i];
            if (w > 0.f) {
                const float4 v = *reinterpret_cast<const float4*>(
                    Vb + (size_t)i * H_ + col);
                acc.x += w * v.x; acc.y += w * v.y;
                acc.z += w * v.z; acc.w += w * v.w;
            }
        }
    }
    *reinterpret_cast<float4*>(out + (size_t)rowg * H_ + col) = acc;
}

// --------------------------------- launch -----------------------------------
extern "C" void kernel_launch(void* const* d_in, const int* in_sizes, int n_in,
                              void* d_out, int out_size)
{
    const float* query = (const float*)d_in[0];   // (B, N, H)
    const float* value = (const float*)d_in[1];   // (B, N, H)
    const int*   mask  = (const int*)d_in[2];     // (B, N, N)
    const float* W     = (const float*)d_in[3];   // (H, H)

    float* out  = (float*)d_out;                   // (B, N, H)
    float* attn = out + (size_t)B_ * N_ * H_;      // (B, N, N)

    __nv_bfloat16 *Qh, *Ql, *Wth, *Wtl, *Vh, *Vl, *Ih, *Il;
    cudaGetSymbolAddress((void**)&Qh,  g_Qh);
    cudaGetSymbolAddress((void**)&Ql,  g_Ql);
    cudaGetSymbolAddress((void**)&Wth, g_Wth);
    cudaGetSymbolAddress((void**)&Wtl, g_Wtl);
    cudaGetSymbolAddress((void**)&Vh,  g_Vh);
    cudaGetSymbolAddress((void**)&Vl,  g_Vl);
    cudaGetSymbolAddress((void**)&Ih,  g_Ih);
    cudaGetSymbolAddress((void**)&Il,  g_Il);

    cudaFuncSetAttribute(gemm_sp<0>, cudaFuncAttributeMaxDynamicSharedMemorySize, SMEM_BYTES);
    cudaFuncSetAttribute(gemm_sp<1>, cudaFuncAttributeMaxDynamicSharedMemorySize, SMEM_BYTES);

    const size_t nQ = (size_t)B_ * N_ * H_;

    split_kernel<<<(unsigned)(nQ / 4 / 256), 256>>>(query, Qh, Ql, nQ);
    split_kernel<<<(unsigned)(nQ / 4 / 256), 256>>>(value, Vh, Vl, nQ);
    tsplit_kernel<<<dim3(H_ / 64, H_ / 64), 256>>>(W, Wth, Wtl, H_, H_);

    // GEMM1: interm = Q @ W -> split bf16
    gemm_sp<0><<<dim3(H_ / 128, (B_ * N_) / 128, 1), 256, SMEM_BYTES>>>(
        Qh, Ql, Wth, Wtl, nullptr, Ih, Il, nullptr,
        H_, H_, 0, 0, 0, 0);

    // GEMM2: logits = mask>0 ? relu(interm @ V^T) : -1e9
    gemm_sp<1><<<dim3(N_ / 128, N_ / 128, B_), 256, SMEM_BYTES>>>(
        Ih, Il, Vh, Vl, attn, nullptr, nullptr, mask,
        H_, N_,
        (size_t)N_ * H_, (size_t)N_ * H_, (size_t)N_ * N_, (size_t)N_ * N_);

    // softmax (in place) + out = attn @ V via sparse gather
    softmax_out_kernel<<<B_ * N_, 256>>>(attn, value, out);
}

// round 7
// speedup vs baseline: 5.0120x; 1.0727x over previous
#include <cuda_runtime.h>
#include <cuda_bf16.h>
#include <cstdint>

// ---------------------------------------------------------------------------
// BilinearAttention, split-bf16 HMMA + register softmax + sparse gather.
//   interm = Q @ W                 GEMM1 (split-bf16 epilogue)
//   logits = mask/relu(interm@V^T) GEMM2 (mask+relu epilogue, fp32)
//   attn   = softmax(logits)       one global read + one write (row in regs)
//   out    = attn @ V              sparse weighted gather (rows are one-hot)
// Output buffer: [ out (B*N*H) | attn (B*N*N) ]
// ---------------------------------------------------------------------------

#define B_   8
#define N_   2048
#define H_   1024

// ------------------------- scratch (no allocations) -------------------------
__device__ __nv_bfloat16 g_Qh[(size_t)B_ * N_ * H_];
__device__ __nv_bfloat16 g_Ql[(size_t)B_ * N_ * H_];
__device__ __nv_bfloat16 g_Wth[(size_t)H_ * H_];
__device__ __nv_bfloat16 g_Wtl[(size_t)H_ * H_];
__device__ __nv_bfloat16 g_Vh[(size_t)B_ * N_ * H_];
__device__ __nv_bfloat16 g_Vl[(size_t)B_ * N_ * H_];
__device__ __nv_bfloat16 g_Ih[(size_t)B_ * N_ * H_];
__device__ __nv_bfloat16 g_Il[(size_t)B_ * N_ * H_];

// ----------------------------- PTX primitives -------------------------------
__device__ __forceinline__ uint32_t smem_u32(const void* p) {
    uint32_t a;
    asm("{ .reg .u64 t; cvta.to.shared.u64 t, %1; cvt.u32.u64 %0, t; }"
        : "=r"(a) : "l"(p));
    return a;
}
__device__ __forceinline__ void cp16(uint32_t dst, const void* src) {
    asm volatile("cp.async.cg.shared.global [%0], [%1], 16;" :: "r"(dst), "l"(src));
}
__device__ __forceinline__ void cp_commit() {
    asm volatile("cp.async.commit_group;" ::: "memory");
}
template<int Nn>
__device__ __forceinline__ void cp_wait() {
    asm volatile("cp.async.wait_group %0;" :: "n"(Nn) : "memory");
}
__device__ __forceinline__ void ldm_x4(uint32_t& r0, uint32_t& r1, uint32_t& r2,
                                       uint32_t& r3, uint32_t addr) {
    asm volatile("ldmatrix.sync.aligned.m8n8.x4.shared.b16 {%0,%1,%2,%3}, [%4];"
                 : "=r"(r0), "=r"(r1), "=r"(r2), "=r"(r3) : "r"(addr));
}
__device__ __forceinline__ void mma16816(float* c, const uint32_t* a, const uint32_t* b) {
    asm volatile(
        "mma.sync.aligned.m16n8k16.row.col.f32.bf16.bf16.f32 "
        "{%0,%1,%2,%3}, {%4,%5,%6,%7}, {%8,%9}, {%0,%1,%2,%3};"
        : "+f"(c[0]), "+f"(c[1]), "+f"(c[2]), "+f"(c[3])
        : "r"(a[0]), "r"(a[1]), "r"(a[2]), "r"(a[3]), "r"(b[0]), "r"(b[1]));
}
__device__ __forceinline__ void stcs_f2(float* p, float2 v) {
    asm volatile("st.global.cs.v2.f32 [%0], {%1, %2};" :: "l"(p), "f"(v.x), "f"(v.y));
}

// ---------------------- split-bf16 tensor-core GEMM --------------------------
// CTA tile 128(M) x 128(N), BK=32. 8 warps, warp tile 32x64.
// Stage 32KB; 3 stages = 96KB; 2 CTAs/SM.
#define A_T   8192
#define STAGE (4 * A_T)
#define SMEM_BYTES (3 * STAGE)

template<int EPI>  // 0: split bf16 hi/lo; 1: mask+relu fp32
__global__ __launch_bounds__(256, 2)
void gemm_sp(const __nv_bfloat16* __restrict__ Ah, const __nv_bfloat16* __restrict__ Al,
             const __nv_bfloat16* __restrict__ Bh, const __nv_bfloat16* __restrict__ Bl,
             float* __restrict__ Cf,
             __nv_bfloat16* __restrict__ Ch, __nv_bfloat16* __restrict__ Cl,
             const int* __restrict__ Mask,
             int K, int ldc,
             size_t sA, size_t sB, size_t sC, size_t sM)
{
    extern __shared__ __align__(1024) char smem[];
    const uint32_t sbase = smem_u32(smem);
    const int tid  = threadIdx.x;
    const int wid  = tid >> 5;
    const int lane = tid & 31;
    const int bm = blockIdx.y * 128;
    const int bn = blockIdx.x * 128;
    const int bz = blockIdx.z;

    Ah += (size_t)bz * sA;  Al += (size_t)bz * sA;
    Bh += (size_t)bz * sB;  Bl += (size_t)bz * sB;

    const int warpM = wid >> 1;
    const int warpN = wid & 1;
    const int nc = K >> 5;

    float acc[2][8][4];
#pragma unroll
    for (int i = 0; i < 2; i++)
#pragma unroll
        for (int j = 0; j < 8; j++)
#pragma unroll
            for (int q = 0; q < 4; q++) acc[i][j][q] = 0.f;

    auto load_chunk = [&](int c) {
        const int kk = c << 5;
        const uint32_t st = sbase + (uint32_t)(c % 3) * STAGE;
#pragma unroll
        for (int i = 0; i < 2; ++i) {
            const int s = tid + i * 256;
            const int row = s >> 2, col = s & 3;
            const uint32_t off =
                (uint32_t)row * 64 + ((uint32_t)(col ^ ((row >> 1) & 3)) << 4);
            const size_t ga = (size_t)(bm + row) * K + kk + col * 8;
            const size_t gb = (size_t)(bn + row) * K + kk + col * 8;
            cp16(st + off, Ah + ga);
            cp16(st + A_T + off, Al + ga);
            cp16(st + 2 * A_T + off, Bh + gb);
            cp16(st + 3 * A_T + off, Bl + gb);
        }
        cp_commit();
    };

    const uint32_t aRow = (uint32_t)(warpM * 32 + (lane & 15));
    const uint32_t aKhi = (uint32_t)(lane >> 4);
    const uint32_t bRow = (uint32_t)(warpN * 64 + ((lane & 16) >> 1) + (lane & 7));
    const uint32_t bKhi = (uint32_t)((lane >> 3) & 1);

    auto compute_chunk = [&](int buf) {
        const uint32_t st  = sbase + (uint32_t)buf * STAGE;
        const uint32_t sAh = st;
        const uint32_t sAl = st + A_T;
        const uint32_t sBh = st + 2 * A_T;
        const uint32_t sBl = st + 3 * A_T;
#pragma unroll
        for (int ks = 0; ks < 2; ++ks) {
            uint32_t ah[2][4], al[2][4], b[8][2];
#pragma unroll
            for (int mt = 0; mt < 2; ++mt) {
                const uint32_t row = aRow + mt * 16;
                const uint32_t seg = ((uint32_t)(ks * 2) + aKhi) ^ ((row >> 1) & 3);
                const uint32_t off = row * 64 + (seg << 4);
                ldm_x4(ah[mt][0], ah[mt][1], ah[mt][2], ah[mt][3], sAh + off);
                ldm_x4(al[mt][0], al[mt][1], al[mt][2], al[mt][3], sAl + off);
            }
#pragma unroll
            for (int nb = 0; nb < 4; ++nb) {
                const uint32_t row = bRow + nb * 16;
                const uint32_t seg = ((uint32_t)(ks * 2) + bKhi) ^ ((row >> 1) & 3);
                ldm_x4(b[nb * 2][0], b[nb * 2][1], b[nb * 2 + 1][0], b[nb * 2 + 1][1],
                       sBh + row * 64 + (seg << 4));
            }
#pragma unroll
            for (int mt = 0; mt < 2; ++mt)
#pragma unroll
                for (int nt = 0; nt < 8; ++nt)
                    mma16816(acc[mt][nt], ah[mt], b[nt]);   // Ah*Bh
#pragma unroll
            for (int mt = 0; mt < 2; ++mt)
#pragma unroll
                for (int nt = 0; nt < 8; ++nt)
                    mma16816(acc[mt][nt], al[mt], b[nt]);   // Al*Bh
#pragma unroll
            for (int nb = 0; nb < 4; ++nb) {
                const uint32_t row = bRow + nb * 16;
                const uint32_t seg = ((uint32_t)(ks * 2) + bKhi) ^ ((row >> 1) & 3);
                ldm_x4(b[nb * 2][0], b[nb * 2][1], b[nb * 2 + 1][0], b[nb * 2 + 1][1],
                       sBl + row * 64 + (seg << 4));
            }
#pragma unroll
            for (int mt = 0; mt < 2; ++mt)
#pragma unroll
                for (int nt = 0; nt < 8; ++nt)
                    mma16816(acc[mt][nt], ah[mt], b[nt]);   // Ah*Bl
        }
    };

    load_chunk(0);
    load_chunk(1);
    for (int c = 0; c < nc; ++c) {
        if (c + 1 < nc) cp_wait<1>(); else cp_wait<0>();
        __syncthreads();
        if (c + 2 < nc) load_chunk(c + 2);
        compute_chunk(c % 3);
    }

    // ------------------------------ epilogue --------------------------------
    const int rBase = bm + warpM * 32 + (lane >> 2);
    const int cBase = bn + warpN * 64 + (lane & 3) * 2;
#pragma unroll
    for (int mt = 0; mt < 2; ++mt) {
#pragma unroll
        for (int half = 0; half < 2; ++half) {
            const int row = rBase + mt * 16 + half * 8;
#pragma unroll
            for (int nt = 0; nt < 8; ++nt) {
                const int col = cBase + nt * 8;
                const float v0 = acc[mt][nt][half * 2 + 0];
                const float v1 = acc[mt][nt][half * 2 + 1];
                if (EPI == 0) {
                    __nv_bfloat16 hv[2], lv[2];
                    hv[0] = __float2bfloat16(v0);
                    lv[0] = __float2bfloat16(v0 - __bfloat162float(hv[0]));
                    hv[1] = __float2bfloat16(v1);
                    lv[1] = __float2bfloat16(v1 - __bfloat162float(hv[1]));
                    *reinterpret_cast<uint32_t*>(Ch + (size_t)row * ldc + col) =
                        *reinterpret_cast<const uint32_t*>(hv);
                    *reinterpret_cast<uint32_t*>(Cl + (size_t)row * ldc + col) =
                        *reinterpret_cast<const uint32_t*>(lv);
                } else {
                    const int2 m = *reinterpret_cast<const int2*>(
                        Mask + (size_t)bz * sM + (size_t)row * ldc + col);
                    float2 v;
                    v.x = m.x > 0 ? fmaxf(v0, 0.f) : -1e9f;
                    v.y = m.y > 0 ? fmaxf(v1, 0.f) : -1e9f;
                    stcs_f2(Cf + (size_t)bz * sC + (size_t)row * ldc + col, v);
                }
            }
        }
    }
}

// --------------------------- conversion kernels -----------------------------
__global__ __launch_bounds__(256)
void split_kernel(const float* __restrict__ x, __nv_bfloat16* __restrict__ h,
                  __nv_bfloat16* __restrict__ l, size_t n)
{
    const size_t i = ((size_t)blockIdx.x * blockDim.x + threadIdx.x) * 4;
    if (i >= n) return;
    const float4 v = *reinterpret_cast<const float4*>(x + i);
    __nv_bfloat16 hv[4], lv[4];
    const float vv[4] = {v.x, v.y, v.z, v.w};
#pragma unroll
    for (int j = 0; j < 4; ++j) {
        const __nv_bfloat16 hh = __float2bfloat16(vv[j]);
        hv[j] = hh;
        lv[j] = __float2bfloat16(vv[j] - __bfloat162float(hh));
    }
    *reinterpret_cast<uint2*>(h + i) = *reinterpret_cast<const uint2*>(hv);
    *reinterpret_cast<uint2*>(l + i) = *reinterpret_cast<const uint2*>(lv);
}

// Transpose+split: in [R,C] -> ht/lt [C,R]
__global__ __launch_bounds__(256)
void tsplit_kernel(const float* __restrict__ x,
                   __nv_bfloat16* __restrict__ ht, __nv_bfloat16* __restrict__ lt,
                   int R, int C)
{
    __shared__ float t[64][65];
    const int r0 = blockIdx.y * 64, c0 = blockIdx.x * 64;
    const int tid = threadIdx.x;

    const int rr = tid >> 4;
    const int cc = (tid & 15) * 4;
#pragma unroll
    for (int i = 0; i < 4; ++i) {
        const int row = rr + i * 16;
        const float4 v = *reinterpret_cast<const float4*>(
            x + (size_t)(r0 + row) * C + c0 + cc);
        t[row][cc] = v.x; t[row][cc + 1] = v.y;
        t[row][cc + 2] = v.z; t[row][cc + 3] = v.w;
    }
    __syncthreads();

#pragma unroll
    for (int i = 0; i < 2; ++i) {
        const int s = tid + i * 256;
        const int orow = s >> 3;
        const int oc = (s & 7) * 8;
        __nv_bfloat16 hv[8], lv[8];
#pragma unroll
        for (int j = 0; j < 8; ++j) {
            const float v = t[oc + j][orow];
            hv[j] = __float2bfloat16(v);
            lv[j] = __float2bfloat16(v - __bfloat162float(hv[j]));
        }
        const size_t o = (size_t)(c0 + orow) * R + r0 + oc;
        *reinterpret_cast<uint4*>(ht + o) = *reinterpret_cast<const uint4*>(hv);
        *reinterpret_cast<uint4*>(lt + o) = *reinterpret_cast<const uint4*>(lv);
    }
}

// ------------------ fused softmax + sparse-gather output --------------------
// One block per row. Row of 2048 logits lives in 8 regs/thread: one global
// read, one global write. Then out[row] = sum of significant w_i * V[i,:].
// Significant list sorted by index for deterministic accumulation order.
#define SIG_CAP 512
__global__ __launch_bounds__(256)
void softmax_out_kernel(float* __restrict__ attn, const float* __restrict__ V,
                        float* __restrict__ out)
{
    const int rowg = blockIdx.x;           // 0 .. B*N-1
    const int bz   = rowg >> 11;           // / N_
    float* p = attn + (size_t)rowg * N_;
    const float* Vb = V + (size_t)bz * N_ * H_;
    const int tid = threadIdx.x;

    __shared__ float red[256];
    __shared__ int   idxs[SIG_CAP];
    __shared__ float wts[SIG_CAP];
    __shared__ int   cnt;
    if (tid == 0) cnt = 0;

    // load row into registers (coalesced, strided by 256)
    float x[8];
#pragma unroll
    for (int j = 0; j < 8; ++j) x[j] = p[tid + j * 256];

    float lmax = x[0];
#pragma unroll
    for (int j = 1; j < 8; ++j) lmax = fmaxf(lmax, x[j]);
    red[tid] = lmax;
    __syncthreads();
#pragma unroll
    for (int s = 128; s > 0; s >>= 1) {
        if (tid < s) red[tid] = fmaxf(red[tid], red[tid + s]);
        __syncthreads();
    }
    const float rmax = red[0];
    __syncthreads();

    float lsum = 0.f;
#pragma unroll
    for (int j = 0; j < 8; ++j) {
        x[j] = __expf(x[j] - rmax);
        lsum += x[j];
    }
    red[tid] = lsum;
    __syncthreads();
#pragma unroll
    for (int s = 128; s > 0; s >>= 1) {
        if (tid < s) red[tid] += red[tid + s];
        __syncthreads();
    }
    const float inv = 1.0f / red[0];
    __syncthreads();

#pragma unroll
    for (int j = 0; j < 8; ++j) {
        const float w = x[j] * inv;
        x[j] = w;
        p[tid + j * 256] = w;                      // single attn write
        if (w > 1e-9f) {
            const int s = atomicAdd(&cnt, 1);
            if (s < SIG_CAP) { idxs[s] = tid + j * 256; wts[s] = w; }
        }
    }
    __syncthreads();

    const int n = cnt;
    // deterministic order: insertion sort by index (n is tiny)
    if (tid == 0 && n > 1 && n <= SIG_CAP) {
        for (int i = 1; i < n; ++i) {
            const int ki = idxs[i]; const float kw = wts[i];
            int j = i - 1;
            while (j >= 0 && idxs[j] > ki) {
                idxs[j + 1] = idxs[j]; wts[j + 1] = wts[j]; --j;
            }
            idxs[j + 1] = ki; wts[j + 1] = kw;
        }
    }
    __syncthreads();

    // gather: each thread owns 4 contiguous output columns
    const int col = tid * 4;
    float4 acc = make_float4(0.f, 0.f, 0.f, 0.f);
    if (n <= SIG_CAP) {
        for (int s = 0; s < n; ++s) {
            const float w = wts[s];
            const float4 v = *reinterpret_cast<const float4*>(
                Vb + (size_t)idxs[s] * H_ + col);
            acc.x += w * v.x; acc.y += w * v.y;
            acc.z += w * v.z; acc.w += w * v.w;
        }
    } else {
        for (int i = 0; i < N_; ++i) {
            const float w = p[i];
            if (w > 0.f) {
                const float4 v = *reinterpret_cast<const float4*>(
                    Vb + (size_t)i * H_ + col);
                acc.x += w * v.x; acc.y += w * v.y;
                acc.z += w * v.z; acc.w += w * v.w;
            }
        }
    }
    *reinterpret_cast<float4*>(out + (size_t)rowg * H_ + col) = acc;
}

// --------------------------------- launch -----------------------------------
extern "C" void kernel_launch(void* const* d_in, const int* in_sizes, int n_in,
                              void* d_out, int out_size)
{
    const float* query = (const float*)d_in[0];   // (B, N, H)
    const float* value = (const float*)d_in[1];   // (B, N, H)
    const int*   mask  = (const int*)d_in[2];     // (B, N, N)
    const float* W     = (const float*)d_in[3];   // (H, H)

    float* out  = (float*)d_out;                   // (B, N, H)
    float* attn = out + (size_t)B_ * N_ * H_;      // (B, N, N)

    __nv_bfloat16 *Qh, *Ql, *Wth, *Wtl, *Vh, *Vl, *Ih, *Il;
    cudaGetSymbolAddress((void**)&Qh,  g_Qh);
    cudaGetSymbolAddress((void**)&Ql,  g_Ql);
    cudaGetSymbolAddress((void**)&Wth, g_Wth);
    cudaGetSymbolAddress((void**)&Wtl, g_Wtl);
    cudaGetSymbolAddress((void**)&Vh,  g_Vh);
    cudaGetSymbolAddress((void**)&Vl,  g_Vl);
    cudaGetSymbolAddress((void**)&Ih,  g_Ih);
    cudaGetSymbolAddress((void**)&Il,  g_Il);

    cudaFuncSetAttribute(gemm_sp<0>, cudaFuncAttributeMaxDynamicSharedMemorySize, SMEM_BYTES);
    cudaFuncSetAttribute(gemm_sp<1>, cudaFuncAttributeMaxDynamicSharedMemorySize, SMEM_BYTES);

    // side stream + events, created once on the (un-captured) correctness call
    static cudaStream_t s2 = nullptr;
    static cudaEvent_t evFork = nullptr, evJoin = nullptr;
    if (!s2) {
        cudaStreamCreateWithFlags(&s2, cudaStreamNonBlocking);
        cudaEventCreateWithFlags(&evFork, cudaEventDisableTiming);
        cudaEventCreateWithFlags(&evJoin, cudaEventDisableTiming);
    }

    const size_t nQ = (size_t)B_ * N_ * H_;

    // fork: V split runs concurrently with Q/W prep + GEMM1
    cudaEventRecord(evFork, 0);
    cudaStreamWaitEvent(s2, evFork, 0);
    split_kernel<<<(unsigned)(nQ / 4 / 256), 256, 0, s2>>>(value, Vh, Vl, nQ);
    cudaEventRecord(evJoin, s2);

    split_kernel<<<(unsigned)(nQ / 4 / 256), 256>>>(query, Qh, Ql, nQ);
    tsplit_kernel<<<dim3(H_ / 64, H_ / 64), 256>>>(W, Wth, Wtl, H_, H_);

    // GEMM1: interm = Q @ W -> split bf16
    gemm_sp<0><<<dim3(H_ / 128, (B_ * N_) / 128, 1), 256, SMEM_BYTES>>>(
        Qh, Ql, Wth, Wtl, nullptr, Ih, Il, nullptr,
        H_, H_, 0, 0, 0, 0);

    // join: GEMM2 needs the V split
    cudaStreamWaitEvent(0, evJoin, 0);

    // GEMM2: logits = mask>0 ? relu(interm @ V^T) : -1e9
    gemm_sp<1><<<dim3(N_ / 128, N_ / 128, B_), 256, SMEM_BYTES>>>(
        Ih, Il, Vh, Vl, attn, nullptr, nullptr, mask,
        H_, N_,
        (size_t)N_ * H_, (size_t)N_ * H_, (size_t)N_ * N_, (size_t)N_ * N_);

    // softmax (in place) + out = attn @ V via sparse gather
    softmax_out_kernel<<<B_ * N_, 256>>>(attn, value, out);
}

// round 9
// speedup vs baseline: 5.1241x; 1.0224x over previous
#include <cuda_runtime.h>
#include <cuda_bf16.h>
#include <cstdint>

// ---------------------------------------------------------------------------
// BilinearAttention, split-bf16 HMMA + register softmax + sparse gather.
//   interm = Q @ W                 GEMM1 (split-bf16 epilogue)
//   logits = mask/relu(interm@V^T) GEMM2 (mask+relu epilogue, fp32)
//   attn   = softmax(logits)       row in registers, 1 read + 1 write
//   out    = attn @ V              sparse weighted gather (rows one-hot)
// Inner GEMM loop register-pipelines Bl fragments (separate regs from Bh).
// Output buffer: [ out (B*N*H) | attn (B*N*N) ]
// ---------------------------------------------------------------------------

#define B_   8
#define N_   2048
#define H_   1024

// ------------------------- scratch (no allocations) -------------------------
__device__ __nv_bfloat16 g_Qh[(size_t)B_ * N_ * H_];
__device__ __nv_bfloat16 g_Ql[(size_t)B_ * N_ * H_];
__device__ __nv_bfloat16 g_Wth[(size_t)H_ * H_];
__device__ __nv_bfloat16 g_Wtl[(size_t)H_ * H_];
__device__ __nv_bfloat16 g_Vh[(size_t)B_ * N_ * H_];
__device__ __nv_bfloat16 g_Vl[(size_t)B_ * N_ * H_];
__device__ __nv_bfloat16 g_Ih[(size_t)B_ * N_ * H_];
__device__ __nv_bfloat16 g_Il[(size_t)B_ * N_ * H_];

// ----------------------------- PTX primitives -------------------------------
__device__ __forceinline__ uint32_t smem_u32(const void* p) {
    uint32_t a;
    asm("{ .reg .u64 t; cvta.to.shared.u64 t, %1; cvt.u32.u64 %0, t; }"
        : "=r"(a) : "l"(p));
    return a;
}
__device__ __forceinline__ void cp16(uint32_t dst, const void* src) {
    asm volatile("cp.async.cg.shared.global [%0], [%1], 16;" :: "r"(dst), "l"(src));
}
__device__ __forceinline__ void cp_commit() {
    asm volatile("cp.async.commit_group;" ::: "memory");
}
template<int Nn>
__device__ __forceinline__ void cp_wait() {
    asm volatile("cp.async.wait_group %0;" :: "n"(Nn) : "memory");
}
__device__ __forceinline__ void ldm_x4(uint32_t& r0, uint32_t& r1, uint32_t& r2,
                                       uint32_t& r3, uint32_t addr) {
    asm volatile("ldmatrix.sync.aligned.m8n8.x4.shared.b16 {%0,%1,%2,%3}, [%4];"
                 : "=r"(r0), "=r"(r1), "=r"(r2), "=r"(r3) : "r"(addr));
}
__device__ __forceinline__ void mma16816(float* c, const uint32_t* a, const uint32_t* b) {
    asm volatile(
        "mma.sync.aligned.m16n8k16.row.col.f32.bf16.bf16.f32 "
        "{%0,%1,%2,%3}, {%4,%5,%6,%7}, {%8,%9}, {%0,%1,%2,%3};"
        : "+f"(c[0]), "+f"(c[1]), "+f"(c[2]), "+f"(c[3])
        : "r"(a[0]), "r"(a[1]), "r"(a[2]), "r"(a[3]), "r"(b[0]), "r"(b[1]));
}
__device__ __forceinline__ void stcs_f2(float* p, float2 v) {
    asm volatile("st.global.cs.v2.f32 [%0], {%1, %2};" :: "l"(p), "f"(v.x), "f"(v.y));
}

// ---------------------- split-bf16 tensor-core GEMM --------------------------
// CTA tile 128(M) x 128(N), BK=32. 8 warps, warp tile 32x64.
// Stage 32KB; 3 stages = 96KB; 2 CTAs/SM.
#define A_T   8192
#define STAGE (4 * A_T)
#define SMEM_BYTES (3 * STAGE)

template<int EPI>  // 0: split bf16 hi/lo; 1: mask+relu fp32
__global__ __launch_bounds__(256, 2)
void gemm_sp(const __nv_bfloat16* __restrict__ Ah, const __nv_bfloat16* __restrict__ Al,
             const __nv_bfloat16* __restrict__ Bh, const __nv_bfloat16* __restrict__ Bl,
             float* __restrict__ Cf,
             __nv_bfloat16* __restrict__ Ch, __nv_bfloat16* __restrict__ Cl,
             const int* __restrict__ Mask,
             int K, int ldc,
             size_t sA, size_t sB, size_t sC, size_t sM)
{
    extern __shared__ __align__(1024) char smem[];
    const uint32_t sbase = smem_u32(smem);
    const int tid  = threadIdx.x;
    const int wid  = tid >> 5;
    const int lane = tid & 31;
    const int bm = blockIdx.y * 128;
    const int bn = blockIdx.x * 128;
    const int bz = blockIdx.z;

    Ah += (size_t)bz * sA;  Al += (size_t)bz * sA;
    Bh += (size_t)bz * sB;  Bl += (size_t)bz * sB;

    const int warpM = wid >> 1;
    const int warpN = wid & 1;
    const int nc = K >> 5;

    float acc[2][8][4];
#pragma unroll
    for (int i = 0; i < 2; i++)
#pragma unroll
        for (int j = 0; j < 8; j++)
#pragma unroll
            for (int q = 0; q < 4; q++) acc[i][j][q] = 0.f;

    auto load_chunk = [&](int c) {
        const int kk = c << 5;
        const uint32_t st = sbase + (uint32_t)(c % 3) * STAGE;
#pragma unroll
        for (int i = 0; i < 2; ++i) {
            const int s = tid + i * 256;
            const int row = s >> 2, col = s & 3;
            const uint32_t off =
                (uint32_t)row * 64 + ((uint32_t)(col ^ ((row >> 1) & 3)) << 4);
            const size_t ga = (size_t)(bm + row) * K + kk + col * 8;
            const size_t gb = (size_t)(bn + row) * K + kk + col * 8;
            cp16(st + off, Ah + ga);
            cp16(st + A_T + off, Al + ga);
            cp16(st + 2 * A_T + off, Bh + gb);
            cp16(st + 3 * A_T + off, Bl + gb);
        }
        cp_commit();
    };

    const uint32_t aRow = (uint32_t)(warpM * 32 + (lane & 15));
    const uint32_t aKhi = (uint32_t)(lane >> 4);
    const uint32_t bRow = (uint32_t)(warpN * 64 + ((lane & 16) >> 1) + (lane & 7));
    const uint32_t bKhi = (uint32_t)((lane >> 3) & 1);

    auto compute_chunk = [&](int buf) {
        const uint32_t st  = sbase + (uint32_t)buf * STAGE;
        const uint32_t sAh = st;
        const uint32_t sAl = st + A_T;
        const uint32_t sBh = st + 2 * A_T;
        const uint32_t sBl = st + 3 * A_T;
#pragma unroll
        for (int ks = 0; ks < 2; ++ks) {
            uint32_t ah[2][4], al[2][4], bh[8][2], bl[8][2];
#pragma unroll
            for (int mt = 0; mt < 2; ++mt) {
                const uint32_t row = aRow + mt * 16;
                const uint32_t seg = ((uint32_t)(ks * 2) + aKhi) ^ ((row >> 1) & 3);
                const uint32_t off = row * 64 + (seg << 4);
                ldm_x4(ah[mt][0], ah[mt][1], ah[mt][2], ah[mt][3], sAh + off);
                ldm_x4(al[mt][0], al[mt][1], al[mt][2], al[mt][3], sAl + off);
            }
#pragma unroll
            for (int nb = 0; nb < 4; ++nb) {
                const uint32_t row = bRow + nb * 16;
                const uint32_t seg = ((uint32_t)(ks * 2) + bKhi) ^ ((row >> 1) & 3);
                ldm_x4(bh[nb * 2][0], bh[nb * 2][1], bh[nb * 2 + 1][0], bh[nb * 2 + 1][1],
                       sBh + row * 64 + (seg << 4));
            }
            // Bl into separate registers: overlaps the next two MMA passes
#pragma unroll
            for (int nb = 0; nb < 4; ++nb) {
                const uint32_t row = bRow + nb * 16;
                const uint32_t seg = ((uint32_t)(ks * 2) + bKhi) ^ ((row >> 1) & 3);
                ldm_x4(bl[nb * 2][0], bl[nb * 2][1], bl[nb * 2 + 1][0], bl[nb * 2 + 1][1],
                       sBl + row * 64 + (seg << 4));
            }
#pragma unroll
            for (int mt = 0; mt < 2; ++mt)
#pragma unroll
                for (int nt = 0; nt < 8; ++nt)
                    mma16816(acc[mt][nt], ah[mt], bh[nt]);   // Ah*Bh
#pragma unroll
            for (int mt = 0; mt < 2; ++mt)
#pragma unroll
                for (int nt = 0; nt < 8; ++nt)
                    mma16816(acc[mt][nt], al[mt], bh[nt]);   // Al*Bh
#pragma unroll
            for (int mt = 0; mt < 2; ++mt)
#pragma unroll
                for (int nt = 0; nt < 8; ++nt)
                    mma16816(acc[mt][nt], ah[mt], bl[nt]);   // Ah*Bl
        }
    };

    load_chunk(0);
    load_chunk(1);
    for (int c = 0; c < nc; ++c) {
        if (c + 1 < nc) cp_wait<1>(); else cp_wait<0>();
        __syncthreads();
        if (c + 2 < nc) load_chunk(c + 2);
        compute_chunk(c % 3);
    }

    // ------------------------------ epilogue --------------------------------
    const int rBase = bm + warpM * 32 + (lane >> 2);
    const int cBase = bn + warpN * 64 + (lane & 3) * 2;
#pragma unroll
    for (int mt = 0; mt < 2; ++mt) {
#pragma unroll
        for (int half = 0; half < 2; ++half) {
            const int row = rBase + mt * 16 + half * 8;
#pragma unroll
            for (int nt = 0; nt < 8; ++nt) {
                const int col = cBase + nt * 8;
                const float v0 = acc[mt][nt][half * 2 + 0];
                const float v1 = acc[mt][nt][half * 2 + 1];
                if (EPI == 0) {
                    __nv_bfloat16 hv[2], lv[2];
                    hv[0] = __float2bfloat16(v0);
                    lv[0] = __float2bfloat16(v0 - __bfloat162float(hv[0]));
                    hv[1] = __float2bfloat16(v1);
                    lv[1] = __float2bfloat16(v1 - __bfloat162float(hv[1]));
                    *reinterpret_cast<uint32_t*>(Ch + (size_t)row * ldc + col) =
                        *reinterpret_cast<const uint32_t*>(hv);
                    *reinterpret_cast<uint32_t*>(Cl + (size_t)row * ldc + col) =
                        *reinterpret_cast<const uint32_t*>(lv);
                } else {
                    const int2 m = *reinterpret_cast<const int2*>(
                        Mask + (size_t)bz * sM + (size_t)row * ldc + col);
                    float2 v;
                    v.x = m.x > 0 ? fmaxf(v0, 0.f) : -1e9f;
                    v.y = m.y > 0 ? fmaxf(v1, 0.f) : -1e9f;
                    stcs_f2(Cf + (size_t)bz * sC + (size_t)row * ldc + col, v);
                }
            }
        }
    }
}

// --------------------------- conversion kernels -----------------------------
__global__ __launch_bounds__(256)
void split_kernel(const float* __restrict__ x, __nv_bfloat16* __restrict__ h,
                  __nv_bfloat16* __restrict__ l, size_t n)
{
    const size_t i = ((size_t)blockIdx.x * blockDim.x + threadIdx.x) * 4;
    if (i >= n) return;
    const float4 v = *reinterpret_cast<const float4*>(x + i);
    __nv_bfloat16 hv[4], lv[4];
    const float vv[4] = {v.x, v.y, v.z, v.w};
#pragma unroll
    for (int j = 0; j < 4; ++j) {
        const __nv_bfloat16 hh = __float2bfloat16(vv[j]);
        hv[j] = hh;
        lv[j] = __float2bfloat16(vv[j] - __bfloat162float(hh));
    }
    *reinterpret_cast<uint2*>(h + i) = *reinterpret_cast<const uint2*>(hv);
    *reinterpret_cast<uint2*>(l + i) = *reinterpret_cast<const uint2*>(lv);
}

// Transpose+split: in [R,C] -> ht/lt [C,R]
__global__ __launch_bounds__(256)
void tsplit_kernel(const float* __restrict__ x,
                   __nv_bfloat16* __restrict__ ht, __nv_bfloat16* __restrict__ lt,
                   int R, int C)
{
    __shared__ float t[64][65];
    const int r0 = blockIdx.y * 64, c0 = blockIdx.x * 64;
    const int tid = threadIdx.x;

    const int rr = tid >> 4;
    const int cc = (tid & 15) * 4;
#pragma unroll
    for (int i = 0; i < 4; ++i) {
        const int row = rr + i * 16;
        const float4 v = *reinterpret_cast<const float4*>(
            x + (size_t)(r0 + row) * C + c0 + cc);
        t[row][cc] = v.x; t[row][cc + 1] = v.y;
        t[row][cc + 2] = v.z; t[row][cc + 3] = v.w;
    }
    __syncthreads();

#pragma unroll
    for (int i = 0; i < 2; ++i) {
        const int s = tid + i * 256;
        const int orow = s >> 3;
        const int oc = (s & 7) * 8;
        __nv_bfloat16 hv[8], lv[8];
#pragma unroll
        for (int j = 0; j < 8; ++j) {
            const float v = t[oc + j][orow];
            hv[j] = __float2bfloat16(v);
            lv[j] = __float2bfloat16(v - __bfloat162float(hv[j]));
        }
        const size_t o = (size_t)(c0 + orow) * R + r0 + oc;
        *reinterpret_cast<uint4*>(ht + o) = *reinterpret_cast<const uint4*>(hv);
        *reinterpret_cast<uint4*>(lt + o) = *reinterpret_cast<const uint4*>(lv);
    }
}

// ------------------ fused softmax + sparse-gather output --------------------
#define SIG_CAP 512
__global__ __launch_bounds__(256)
void softmax_out_kernel(float* __restrict__ attn, const float* __restrict__ V,
                        float* __restrict__ out)
{
    const int rowg = blockIdx.x;           // 0 .. B*N-1
    const int bz   = rowg >> 11;           // / N_
    float* p = attn + (size_t)rowg * N_;
    const float* Vb = V + (size_t)bz * N_ * H_;
    const int tid = threadIdx.x;

    __shared__ float red[256];
    __shared__ int   idxs[SIG_CAP];
    __shared__ float wts[SIG_CAP];
    __shared__ int   cnt;
    if (tid == 0) cnt = 0;

    float x[8];
#pragma unroll
    for (int j = 0; j < 8; ++j) x[j] = p[tid + j * 256];

    float lmax = x[0];
#pragma unroll
    for (int j = 1; j < 8; ++j) lmax = fmaxf(lmax, x[j]);
    red[tid] = lmax;
    __syncthreads();
#pragma unroll
    for (int s = 128; s > 0; s >>= 1) {
        if (tid < s) red[tid] = fmaxf(red[tid], red[tid + s]);
        __syncthreads();
    }
    const float rmax = red[0];
    __syncthreads();

    float lsum = 0.f;
#pragma unroll
    for (int j = 0; j < 8; ++j) {
        x[j] = __expf(x[j] - rmax);
        lsum += x[j];
    }
    red[tid] = lsum;
    __syncthreads();
#pragma unroll
    for (int s = 128; s > 0; s >>= 1) {
        if (tid < s) red[tid] += red[tid + s];
        __syncthreads();
    }
    const float inv = 1.0f / red[0];
    __syncthreads();

#pragma unroll
    for (int j = 0; j < 8; ++j) {
        const float w = x[j] * inv;
        x[j] = w;
        p[tid + j * 256] = w;
        if (w > 1e-9f) {
            const int s = atomicAdd(&cnt, 1);
            if (s < SIG_CAP) { idxs[s] = tid + j * 256; wts[s] = w; }
        }
    }
    __syncthreads();

    const int n = cnt;
    if (tid == 0 && n > 1 && n <= SIG_CAP) {
        for (int i = 1; i < n; ++i) {
            const int ki = idxs[i]; const float kw = wts[i];
            int j = i - 1;
            while (j >= 0 && idxs[j] > ki) {
                idxs[j + 1] = idxs[j]; wts[j + 1] = wts[j]; --j;
            }
            idxs[j + 1] = ki; wts[j + 1] = kw;
        }
    }
    __syncthreads();

    const int col = tid * 4;
    float4 acc = make_float4(0.f, 0.f, 0.f, 0.f);
    if (n <= SIG_CAP) {
        for (int s = 0; s < n; ++s) {
            const float w = wts[s];
            const float4 v = *reinterpret_cast<const float4*>(
                Vb + (size_t)idxs[s] * H_ + col);
            acc.x += w * v.x; acc.y += w * v.y;
            acc.z += w * v.z; acc.w += w * v.w;
        }
    } else {
        for (int i = 0; i < N_; ++i) {
            const float w = p[i];
            if (w > 0.f) {
                const float4 v = *reinterpret_cast<const float4*>(
                    Vb + (size_t)i * H_ + col);
                acc.x += w * v.x; acc.y += w * v.y;
                acc.z += w * v.z; acc.w += w * v.w;
            }
        }
    }
    *reinterpret_cast<float4*>(out + (size_t)rowg * H_ + col) = acc;
}

// --------------------------------- launch -----------------------------------
extern "C" void kernel_launch(void* const* d_in, const int* in_sizes, int n_in,
                              void* d_out, int out_size)
{
    const float* query = (const float*)d_in[0];   // (B, N, H)
    const float* value = (const float*)d_in[1];   // (B, N, H)
    const int*   mask  = (const int*)d_in[2];     // (B, N, N)
    const float* W     = (const float*)d_in[3];   // (H, H)

    float* out  = (float*)d_out;                   // (B, N, H)
    float* attn = out + (size_t)B_ * N_ * H_;      // (B, N, N)

    __nv_bfloat16 *Qh, *Ql, *Wth, *Wtl, *Vh, *Vl, *Ih, *Il;
    cudaGetSymbolAddress((void**)&Qh,  g_Qh);
    cudaGetSymbolAddress((void**)&Ql,  g_Ql);
    cudaGetSymbolAddress((void**)&Wth, g_Wth);
    cudaGetSymbolAddress((void**)&Wtl, g_Wtl);
    cudaGetSymbolAddress((void**)&Vh,  g_Vh);
    cudaGetSymbolAddress((void**)&Vl,  g_Vl);
    cudaGetSymbolAddress((void**)&Ih,  g_Ih);
    cudaGetSymbolAddress((void**)&Il,  g_Il);

    cudaFuncSetAttribute(gemm_sp<0>, cudaFuncAttributeMaxDynamicSharedMemorySize, SMEM_BYTES);
    cudaFuncSetAttribute(gemm_sp<1>, cudaFuncAttributeMaxDynamicSharedMemorySize, SMEM_BYTES);

    // one side stream + two events (R7-proven allocation footprint)
    static cudaStream_t s2 = nullptr;
    static cudaEvent_t evFork = nullptr, evJoin = nullptr;
    if (!s2) {
        cudaStreamCreateWithFlags(&s2, cudaStreamNonBlocking);
        cudaEventCreateWithFlags(&evFork, cudaEventDisableTiming);
        cudaEventCreateWithFlags(&evJoin, cudaEventDisableTiming);
    }

    const size_t nQ = (size_t)B_ * N_ * H_;

    // fork: V split runs concurrently with Q/W prep + GEMM1
    cudaEventRecord(evFork, 0);
    cudaStreamWaitEvent(s2, evFork, 0);
    split_kernel<<<(unsigned)(nQ / 4 / 256), 256, 0, s2>>>(value, Vh, Vl, nQ);
    cudaEventRecord(evJoin, s2);

    split_kernel<<<(unsigned)(nQ / 4 / 256), 256>>>(query, Qh, Ql, nQ);
    tsplit_kernel<<<dim3(H_ / 64, H_ / 64), 256>>>(W, Wth, Wtl, H_, H_);

    // GEMM1: interm = Q @ W -> split bf16
    gemm_sp<0><<<dim3(H_ / 128, (B_ * N_) / 128, 1), 256, SMEM_BYTES>>>(
        Qh, Ql, Wth, Wtl, nullptr, Ih, Il, nullptr,
        H_, H_, 0, 0, 0, 0);

    // join: GEMM2 needs the V split
    cudaStreamWaitEvent(0, evJoin, 0);

    // GEMM2: logits = mask>0 ? relu(interm @ V^T) : -1e9
    gemm_sp<1><<<dim3(N_ / 128, N_ / 128, B_), 256, SMEM_BYTES>>>(
        Ih, Il, Vh, Vl, attn, nullptr, nullptr, mask,
        H_, N_,
        (size_t)N_ * H_, (size_t)N_ * H_, (size_t)N_ * N_, (size_t)N_ * N_);

    // softmax (in place) + out = attn @ V via sparse gather
    softmax_out_kernel<<<B_ * N_, 256>>>(attn, value, out);
}

// round 10
// speedup vs baseline: 5.3605x; 1.0461x over previous
#include <cuda_runtime.h>
#include <cuda_bf16.h>
#include <cstdint>

// ---------------------------------------------------------------------------
// BilinearAttention, split-bf16 HMMA + register softmax + sparse gather.
// Two-chain batch pipeline: chain A = batches 0-3 (default stream),
// chain B = batches 4-7 (side stream). 1 stream + 2 re-recorded events
// (proven allocation footprint). Kernels identical to R9.
// Output buffer: [ out (B*N*H) | attn (B*N*N) ]
// ---------------------------------------------------------------------------

#define B_   8
#define N_   2048
#define H_   1024

// ------------------------- scratch (no allocations) -------------------------
__device__ __nv_bfloat16 g_Qh[(size_t)B_ * N_ * H_];
__device__ __nv_bfloat16 g_Ql[(size_t)B_ * N_ * H_];
__device__ __nv_bfloat16 g_Wth[(size_t)H_ * H_];
__device__ __nv_bfloat16 g_Wtl[(size_t)H_ * H_];
__device__ __nv_bfloat16 g_Vh[(size_t)B_ * N_ * H_];
__device__ __nv_bfloat16 g_Vl[(size_t)B_ * N_ * H_];
__device__ __nv_bfloat16 g_Ih[(size_t)B_ * N_ * H_];
__device__ __nv_bfloat16 g_Il[(size_t)B_ * N_ * H_];

// ----------------------------- PTX primitives -------------------------------
__device__ __forceinline__ uint32_t smem_u32(const void* p) {
    uint32_t a;
    asm("{ .reg .u64 t; cvta.to.shared.u64 t, %1; cvt.u32.u64 %0, t; }"
        : "=r"(a) : "l"(p));
    return a;
}
__device__ __forceinline__ void cp16(uint32_t dst, const void* src) {
    asm volatile("cp.async.cg.shared.global [%0], [%1], 16;" :: "r"(dst), "l"(src));
}
__device__ __forceinline__ void cp_commit() {
    asm volatile("cp.async.commit_group;" ::: "memory");
}
template<int Nn>
__device__ __forceinline__ void cp_wait() {
    asm volatile("cp.async.wait_group %0;" :: "n"(Nn) : "memory");
}
__device__ __forceinline__ void ldm_x4(uint32_t& r0, uint32_t& r1, uint32_t& r2,
                                       uint32_t& r3, uint32_t addr) {
    asm volatile("ldmatrix.sync.aligned.m8n8.x4.shared.b16 {%0,%1,%2,%3}, [%4];"
                 : "=r"(r0), "=r"(r1), "=r"(r2), "=r"(r3) : "r"(addr));
}
__device__ __forceinline__ void mma16816(float* c, const uint32_t* a, const uint32_t* b) {
    asm volatile(
        "mma.sync.aligned.m16n8k16.row.col.f32.bf16.bf16.f32 "
        "{%0,%1,%2,%3}, {%4,%5,%6,%7}, {%8,%9}, {%0,%1,%2,%3};"
        : "+f"(c[0]), "+f"(c[1]), "+f"(c[2]), "+f"(c[3])
        : "r"(a[0]), "r"(a[1]), "r"(a[2]), "r"(a[3]), "r"(b[0]), "r"(b[1]));
}
__device__ __forceinline__ void stcs_f2(float* p, float2 v) {
    asm volatile("st.global.cs.v2.f32 [%0], {%1, %2};" :: "l"(p), "f"(v.x), "f"(v.y));
}

// ---------------------- split-bf16 tensor-core GEMM --------------------------
// CTA tile 128(M) x 128(N), BK=32. 8 warps, warp tile 32x64.
// Stage 32KB; 3 stages = 96KB; 2 CTAs/SM.
#define A_T   8192
#define STAGE (4 * A_T)
#define SMEM_BYTES (3 * STAGE)

template<int EPI>  // 0: split bf16 hi/lo; 1: mask+relu fp32
__global__ __launch_bounds__(256, 2)
void gemm_sp(const __nv_bfloat16* __restrict__ Ah, const __nv_bfloat16* __restrict__ Al,
             const __nv_bfloat16* __restrict__ Bh, const __nv_bfloat16* __restrict__ Bl,
             float* __restrict__ Cf,
             __nv_bfloat16* __restrict__ Ch, __nv_bfloat16* __restrict__ Cl,
             const int* __restrict__ Mask,
             int K, int ldc,
             size_t sA, size_t sB, size_t sC, size_t sM)
{
    extern __shared__ __align__(1024) char smem[];
    const uint32_t sbase = smem_u32(smem);
    const int tid  = threadIdx.x;
    const int wid  = tid >> 5;
    const int lane = tid & 31;
    const int bm = blockIdx.y * 128;
    const int bn = blockIdx.x * 128;
    const int bz = blockIdx.z;

    Ah += (size_t)bz * sA;  Al += (size_t)bz * sA;
    Bh += (size_t)bz * sB;  Bl += (size_t)bz * sB;

    const int warpM = wid >> 1;
    const int warpN = wid & 1;
    const int nc = K >> 5;

    float acc[2][8][4];
#pragma unroll
    for (int i = 0; i < 2; i++)
#pragma unroll
        for (int j = 0; j < 8; j++)
#pragma unroll
            for (int q = 0; q < 4; q++) acc[i][j][q] = 0.f;

    auto load_chunk = [&](int c) {
        const int kk = c << 5;
        const uint32_t st = sbase + (uint32_t)(c % 3) * STAGE;
#pragma unroll
        for (int i = 0; i < 2; ++i) {
            const int s = tid + i * 256;
            const int row = s >> 2, col = s & 3;
            const uint32_t off =
                (uint32_t)row * 64 + ((uint32_t)(col ^ ((row >> 1) & 3)) << 4);
            const size_t ga = (size_t)(bm + row) * K + kk + col * 8;
            const size_t gb = (size_t)(bn + row) * K + kk + col * 8;
            cp16(st + off, Ah + ga);
            cp16(st + A_T + off, Al + ga);
            cp16(st + 2 * A_T + off, Bh + gb);
            cp16(st + 3 * A_T + off, Bl + gb);
        }
        cp_commit();
    };

    const uint32_t aRow = (uint32_t)(warpM * 32 + (lane & 15));
    const uint32_t aKhi = (uint32_t)(lane >> 4);
    const uint32_t bRow = (uint32_t)(warpN * 64 + ((lane & 16) >> 1) + (lane & 7));
    const uint32_t bKhi = (uint32_t)((lane >> 3) & 1);

    auto compute_chunk = [&](int buf) {
        const uint32_t st  = sbase + (uint32_t)buf * STAGE;
        const uint32_t sAh = st;
        const uint32_t sAl = st + A_T;
        const uint32_t sBh = st + 2 * A_T;
        const uint32_t sBl = st + 3 * A_T;
#pragma unroll
        for (int ks = 0; ks < 2; ++ks) {
            uint32_t ah[2][4], al[2][4], bh[8][2], bl[8][2];
#pragma unroll
            for (int mt = 0; mt < 2; ++mt) {
                const uint32_t row = aRow + mt * 16;
                const uint32_t seg = ((uint32_t)(ks * 2) + aKhi) ^ ((row >> 1) & 3);
                const uint32_t off = row * 64 + (seg << 4);
                ldm_x4(ah[mt][0], ah[mt][1], ah[mt][2], ah[mt][3], sAh + off);
                ldm_x4(al[mt][0], al[mt][1], al[mt][2], al[mt][3], sAl + off);
            }
#pragma unroll
            for (int nb = 0; nb < 4; ++nb) {
                const uint32_t row = bRow + nb * 16;
                const uint32_t seg = ((uint32_t)(ks * 2) + bKhi) ^ ((row >> 1) & 3);
                ldm_x4(bh[nb * 2][0], bh[nb * 2][1], bh[nb * 2 + 1][0], bh[nb * 2 + 1][1],
                       sBh + row * 64 + (seg << 4));
            }
            // Bl into separate registers: overlaps the next two MMA passes
#pragma unroll
            for (int nb = 0; nb < 4; ++nb) {
                const uint32_t row = bRow + nb * 16;
                const uint32_t seg = ((uint32_t)(ks * 2) + bKhi) ^ ((row >> 1) & 3);
                ldm_x4(bl[nb * 2][0], bl[nb * 2][1], bl[nb * 2 + 1][0], bl[nb * 2 + 1][1],
                       sBl + row * 64 + (seg << 4));
            }
#pragma unroll
            for (int mt = 0; mt < 2; ++mt)
#pragma unroll
                for (int nt = 0; nt < 8; ++nt)
                    mma16816(acc[mt][nt], ah[mt], bh[nt]);   // Ah*Bh
#pragma unroll
            for (int mt = 0; mt < 2; ++mt)
#pragma unroll
                for (int nt = 0; nt < 8; ++nt)
                    mma16816(acc[mt][nt], al[mt], bh[nt]);   // Al*Bh
#pragma unroll
            for (int mt = 0; mt < 2; ++mt)
#pragma unroll
                for (int nt = 0; nt < 8; ++nt)
                    mma16816(acc[mt][nt], ah[mt], bl[nt]);   // Ah*Bl
        }
    };

    load_chunk(0);
    load_chunk(1);
    for (int c = 0; c < nc; ++c) {
        if (c + 1 < nc) cp_wait<1>(); else cp_wait<0>();
        __syncthreads();
        if (c + 2 < nc) load_chunk(c + 2);
        compute_chunk(c % 3);
    }

    // ------------------------------ epilogue --------------------------------
    const int rBase = bm + warpM * 32 + (lane >> 2);
    const int cBase = bn + warpN * 64 + (lane & 3) * 2;
#pragma unroll
    for (int mt = 0; mt < 2; ++mt) {
#pragma unroll
        for (int half = 0; half < 2; ++half) {
            const int row = rBase + mt * 16 + half * 8;
#pragma unroll
            for (int nt = 0; nt < 8; ++nt) {
                const int col = cBase + nt * 8;
                const float v0 = acc[mt][nt][half * 2 + 0];
                const float v1 = acc[mt][nt][half * 2 + 1];
                if (EPI == 0) {
                    __nv_bfloat16 hv[2], lv[2];
                    hv[0] = __float2bfloat16(v0);
                    lv[0] = __float2bfloat16(v0 - __bfloat162float(hv[0]));
                    hv[1] = __float2bfloat16(v1);
                    lv[1] = __float2bfloat16(v1 - __bfloat162float(hv[1]));
                    *reinterpret_cast<uint32_t*>(Ch + (size_t)row * ldc + col) =
                        *reinterpret_cast<const uint32_t*>(hv);
                    *reinterpret_cast<uint32_t*>(Cl + (size_t)row * ldc + col) =
                        *reinterpret_cast<const uint32_t*>(lv);
                } else {
                    const int2 m = *reinterpret_cast<const int2*>(
                        Mask + (size_t)bz * sM + (size_t)row * ldc + col);
                    float2 v;
                    v.x = m.x > 0 ? fmaxf(v0, 0.f) : -1e9f;
                    v.y = m.y > 0 ? fmaxf(v1, 0.f) : -1e9f;
                    stcs_f2(Cf + (size_t)bz * sC + (size_t)row * ldc + col, v);
                }
            }
        }
    }
}

// --------------------------- conversion kernels -----------------------------
__global__ __launch_bounds__(256)
void split_kernel(const float* __restrict__ x, __nv_bfloat16* __restrict__ h,
                  __nv_bfloat16* __restrict__ l, size_t n)
{
    const size_t i = ((size_t)blockIdx.x * blockDim.x + threadIdx.x) * 4;
    if (i >= n) return;
    const float4 v = *reinterpret_cast<const float4*>(x + i);
    __nv_bfloat16 hv[4], lv[4];
    const float vv[4] = {v.x, v.y, v.z, v.w};
#pragma unroll
    for (int j = 0; j < 4; ++j) {
        const __nv_bfloat16 hh = __float2bfloat16(vv[j]);
        hv[j] = hh;
        lv[j] = __float2bfloat16(vv[j] - __bfloat162float(hh));
    }
    *reinterpret_cast<uint2*>(h + i) = *reinterpret_cast<const uint2*>(hv);
    *reinterpret_cast<uint2*>(l + i) = *reinterpret_cast<const uint2*>(lv);
}

// Transpose+split: in [R,C] -> ht/lt [C,R]
__global__ __launch_bounds__(256)
void tsplit_kernel(const float* __restrict__ x,
                   __nv_bfloat16* __restrict__ ht, __nv_bfloat16* __restrict__ lt,
                   int R, int C)
{
    __shared__ float t[64][65];
    const int r0 = blockIdx.y * 64, c0 = blockIdx.x * 64;
    const int tid = threadIdx.x;

    const int rr = tid >> 4;
    const int cc = (tid & 15) * 4;
#pragma unroll
    for (int i = 0; i < 4; ++i) {
        const int row = rr + i * 16;
        const float4 v = *reinterpret_cast<const float4*>(
            x + (size_t)(r0 + row) * C + c0 + cc);
        t[row][cc] = v.x; t[row][cc + 1] = v.y;
        t[row][cc + 2] = v.z; t[row][cc + 3] = v.w;
    }
    __syncthreads();

#pragma unroll
    for (int i = 0; i < 2; ++i) {
        const int s = tid + i * 256;
        const int orow = s >> 3;
        const int oc = (s & 7) * 8;
        __nv_bfloat16 hv[8], lv[8];
#pragma unroll
        for (int j = 0; j < 8; ++j) {
            const float v = t[oc + j][orow];
            hv[j] = __float2bfloat16(v);
            lv[j] = __float2bfloat16(v - __bfloat162float(hv[j]));
        }
        const size_t o = (size_t)(c0 + orow) * R + r0 + oc;
        *reinterpret_cast<uint4*>(ht + o) = *reinterpret_cast<const uint4*>(hv);
        *reinterpret_cast<uint4*>(lt + o) = *reinterpret_cast<const uint4*>(lv);
    }
}

// ------------------ fused softmax + sparse-gather output --------------------
// Pointers may be slab-offset; bz computed relative to the slab start.
#define SIG_CAP 512
__global__ __launch_bounds__(256)
void softmax_out_kernel(float* __restrict__ attn, const float* __restrict__ V,
                        float* __restrict__ out)
{
    const int rowg = blockIdx.x;           // 0 .. (slabBatches*N)-1
    const int bz   = rowg >> 11;           // / N_
    float* p = attn + (size_t)rowg * N_;
    const float* Vb = V + (size_t)bz * N_ * H_;
    const int tid = threadIdx.x;

    __shared__ float red[256];
    __shared__ int   idxs[SIG_CAP];
    __shared__ float wts[SIG_CAP];
    __shared__ int   cnt;
    if (tid == 0) cnt = 0;

    float x[8];
#pragma unroll
    for (int j = 0; j < 8; ++j) x[j] = p[tid + j * 256];

    float lmax = x[0];
#pragma unroll
    for (int j = 1; j < 8; ++j) lmax = fmaxf(lmax, x[j]);
    red[tid] = lmax;
    __syncthreads();
#pragma unroll
    for (int s = 128; s > 0; s >>= 1) {
        if (tid < s) red[tid] = fmaxf(red[tid], red[tid + s]);
        __syncthreads();
    }
    const float rmax = red[0];
    __syncthreads();

    float lsum = 0.f;
#pragma unroll
    for (int j = 0; j < 8; ++j) {
        x[j] = __expf(x[j] - rmax);
        lsum += x[j];
    }
    red[tid] = lsum;
    __syncthreads();
#pragma unroll
    for (int s = 128; s > 0; s >>= 1) {
        if (tid < s) red[tid] += red[tid + s];
        __syncthreads();
    }
    const float inv = 1.0f / red[0];
    __syncthreads();

#pragma unroll
    for (int j = 0; j < 8; ++j) {
        const float w = x[j] * inv;
        x[j] = w;
        p[tid + j * 256] = w;
        if (w > 1e-9f) {
            const int s = atomicAdd(&cnt, 1);
            if (s < SIG_CAP) { idxs[s] = tid + j * 256; wts[s] = w; }
        }
    }
    __syncthreads();

    const int n = cnt;
    if (tid == 0 && n > 1 && n <= SIG_CAP) {
        for (int i = 1; i < n; ++i) {
            const int ki = idxs[i]; const float kw = wts[i];
            int j = i - 1;
            while (j >= 0 && idxs[j] > ki) {
                idxs[j + 1] = idxs[j]; wts[j + 1] = wts[j]; --j;
            }
            idxs[j + 1] = ki; wts[j + 1] = kw;
        }
    }
    __syncthreads();

    const int col = tid * 4;
    float4 acc = make_float4(0.f, 0.f, 0.f, 0.f);
    if (n <= SIG_CAP) {
        for (int s = 0; s < n; ++s) {
            const float w = wts[s];
            const float4 v = *reinterpret_cast<const float4*>(
                Vb + (size_t)idxs[s] * H_ + col);
            acc.x += w * v.x; acc.y += w * v.y;
            acc.z += w * v.z; acc.w += w * v.w;
        }
    } else {
        for (int i = 0; i < N_; ++i) {
            const float w = p[i];
            if (w > 0.f) {
                const float4 v = *reinterpret_cast<const float4*>(
                    Vb + (size_t)i * H_ + col);
                acc.x += w * v.x; acc.y += w * v.y;
                acc.z += w * v.z; acc.w += w * v.w;
            }
        }
    }
    *reinterpret_cast<float4*>(out + (size_t)rowg * H_ + col) = acc;
}

// --------------------------------- launch -----------------------------------
extern "C" void kernel_launch(void* const* d_in, const int* in_sizes, int n_in,
                              void* d_out, int out_size)
{
    const float* query = (const float*)d_in[0];   // (B, N, H)
    const float* value = (const float*)d_in[1];   // (B, N, H)
    const int*   mask  = (const int*)d_in[2];     // (B, N, N)
    const float* W     = (const float*)d_in[3];   // (H, H)

    float* out  = (float*)d_out;                   // (B, N, H)
    float* attn = out + (size_t)B_ * N_ * H_;      // (B, N, N)

    __nv_bfloat16 *Qh, *Ql, *Wth, *Wtl, *Vh, *Vl, *Ih, *Il;
    cudaGetSymbolAddress((void**)&Qh,  g_Qh);
    cudaGetSymbolAddress((void**)&Ql,  g_Ql);
    cudaGetSymbolAddress((void**)&Wth, g_Wth);
    cudaGetSymbolAddress((void**)&Wtl, g_Wtl);
    cudaGetSymbolAddress((void**)&Vh,  g_Vh);
    cudaGetSymbolAddress((void**)&Vl,  g_Vl);
    cudaGetSymbolAddress((void**)&Ih,  g_Ih);
    cudaGetSymbolAddress((void**)&Il,  g_Il);

    cudaFuncSetAttribute(gemm_sp<0>, cudaFuncAttributeMaxDynamicSharedMemorySize, SMEM_BYTES);
    cudaFuncSetAttribute(gemm_sp<1>, cudaFuncAttributeMaxDynamicSharedMemorySize, SMEM_BYTES);

    // one side stream + two events (R7/R9-proven allocation footprint);
    // event objects are re-recorded for the later dependencies.
    static cudaStream_t s2 = nullptr;
    static cudaEvent_t evA = nullptr, evB = nullptr;
    if (!s2) {
        cudaStreamCreateWithFlags(&s2, cudaStreamNonBlocking);
        cudaEventCreateWithFlags(&evA, cudaEventDisableTiming);
        cudaEventCreateWithFlags(&evB, cudaEventDisableTiming);
    }

    const size_t nQ  = (size_t)B_ * N_ * H_;
    const size_t bQ  = (size_t)N_ * H_;       // per-batch Q/V/interm elems
    const size_t bAt = (size_t)N_ * N_;       // per-batch attn/mask elems
    const int    HB  = B_ / 2;                // batches per chain
    const size_t oQ  = (size_t)HB * bQ;       // chain-B offsets
    const size_t oAt = (size_t)HB * bAt;

    // 1) fork
    cudaEventRecord(evA, 0);
    cudaStreamWaitEvent(s2, evA, 0);

    // 2) s2: V split; evB = "V ready"
    split_kernel<<<(unsigned)(nQ / 4 / 256), 256, 0, s2>>>(value, Vh, Vl, nQ);
    cudaEventRecord(evB, s2);

    // 3) default: Q split + W transpose; evA (re-record) = "Q/W ready"
    split_kernel<<<(unsigned)(nQ / 4 / 256), 256>>>(query, Qh, Ql, nQ);
    tsplit_kernel<<<dim3(H_ / 64, H_ / 64), 256>>>(W, Wth, Wtl, H_, H_);
    cudaEventRecord(evA, 0);
    cudaStreamWaitEvent(s2, evA, 0);

    // 4) chain A on default: GEMM1(0-3); wait V; GEMM2(0-3); softmax(0-3)
    gemm_sp<0><<<dim3(H_ / 128, (HB * N_) / 128, 1), 256, SMEM_BYTES>>>(
        Qh, Ql, Wth, Wtl, nullptr, Ih, Il, nullptr,
        H_, H_, 0, 0, 0, 0);
    cudaStreamWaitEvent(0, evB, 0);   // V ready (binds to record in step 2)
    gemm_sp<1><<<dim3(N_ / 128, N_ / 128, HB), 256, SMEM_BYTES>>>(
        Ih, Il, Vh, Vl, attn, nullptr, nullptr, mask,
        H_, N_, bQ, bQ, bAt, bAt);
    softmax_out_kernel<<<HB * N_, 256>>>(attn, value, out);

    // 5) chain B on s2: GEMM1(4-7); GEMM2(4-7); softmax(4-7)
    gemm_sp<0><<<dim3(H_ / 128, (HB * N_) / 128, 1), 256, SMEM_BYTES, s2>>>(
        Qh + oQ, Ql + oQ, Wth, Wtl, nullptr, Ih + oQ, Il + oQ, nullptr,
        H_, H_, 0, 0, 0, 0);
    gemm_sp<1><<<dim3(N_ / 128, N_ / 128, HB), 256, SMEM_BYTES, s2>>>(
        Ih + oQ, Il + oQ, Vh + oQ, Vl + oQ, attn + oAt, nullptr, nullptr,
        mask + oAt, H_, N_, bQ, bQ, bAt, bAt);
    softmax_out_kernel<<<HB * N_, 256, 0, s2>>>(
        attn + oAt, value + oQ, out + oQ);

    // 6) join: evB (re-record) = "chain B done"
    cudaEventRecord(evB, s2);
    cudaStreamWaitEvent(0, evB, 0);
}